// round 8
// baseline (speedup 1.0000x reference)
#include <cuda_runtime.h>
#include <cstdint>

#define NMAX 10000
#define EMAX 320000

// ---------------- scratch (static device globals; no allocation) ------------
__device__ int   g_is64;
__device__ float g_dinv[NMAX];
__device__ int   g_cnt[NMAX];
__device__ int   g_off[NMAX + 1];
__device__ int   g_cur[NMAX];
__device__ int   g_src[EMAX];
__device__ float g_wgt[EMAX];
__device__ float g_a [(size_t)NMAX * 512];  // aggregation output (tf32-rounded)
__device__ float g_h [(size_t)NMAX * 768];  // layer activation (post-GEMM)
__device__ float g_wb[512 * 768];           // tf32-rounded weight buffer
__device__ float g_o8[(size_t)NMAX * 8];    // layer-3 GEMM output

// ---------------- fused init + dtype detect ---------------------------------
__global__ void k_init_detect(const int* __restrict__ ei32, int nwords, int n) {
    int i = blockIdx.x * blockDim.x + threadIdx.x;
    if (i < n) { g_dinv[i] = 0.0f; g_cnt[i] = 0; }
    if (blockIdx.x == 0) {
        __shared__ int any_nonzero;
        if (threadIdx.x == 0) any_nonzero = 0;
        __syncthreads();
        int lim = nwords < 2048 ? nwords : 2048;
        for (int w = threadIdx.x * 2 + 1; w < lim; w += 512)
            if (ei32[w] != 0) atomicOr(&any_nonzero, 1);
        __syncthreads();
        if (threadIdx.x == 0) g_is64 = any_nonzero ? 0 : 1;
    }
}

__device__ __forceinline__ int load_idx(const void* ei, long long pos, int n) {
    int v = g_is64 ? (int)((const long long*)ei)[pos]
                   : ((const int*)ei)[pos];
    v = v < 0 ? 0 : (v >= n ? n - 1 : v);
    return v;
}

__global__ void k_deg(const void* __restrict__ ei,
                      const float* __restrict__ ew, int E, int n) {
    int e = blockIdx.x * blockDim.x + threadIdx.x;
    if (e >= E) return;
    int c = load_idx(ei, (long long)E + e, n);
    atomicAdd(&g_dinv[c], ew[e]);
    atomicAdd(&g_cnt[c], 1);
}

// scan (single block) + fold in dinv computation
__global__ void k_scan(int n) {
    __shared__ int part[1024];
    int t = threadIdx.x;
    for (int i = t; i < n; i += 1024)
        g_dinv[i] = rsqrtf(g_dinv[i] + 1.0f);
    int per = (n + 1023) / 1024;
    int base = t * per;
    int s = 0;
    for (int i = 0; i < per; i++) {
        int idx = base + i;
        if (idx < n) s += g_cnt[idx];
    }
    part[t] = s;
    __syncthreads();
    for (int d = 1; d < 1024; d <<= 1) {
        int v = (t >= d) ? part[t - d] : 0;
        __syncthreads();
        part[t] += v;
        __syncthreads();
    }
    int run = (t == 0) ? 0 : part[t - 1];
    for (int i = 0; i < per; i++) {
        int idx = base + i;
        if (idx < n) {
            g_off[idx] = run;
            g_cur[idx] = run;
            run += g_cnt[idx];
        }
    }
    if (t == 1023) g_off[n] = part[1023];
}

__global__ void k_scatter(const void* __restrict__ ei,
                          const float* __restrict__ ew, int E, int n) {
    int e = blockIdx.x * blockDim.x + threadIdx.x;
    if (e >= E) return;
    int r = load_idx(ei, e, n);
    int c = load_idx(ei, (long long)E + e, n);
    int p = atomicAdd(&g_cur[c], 1);
    if (p < EMAX) {
        g_src[p] = r;
        g_wgt[p] = g_dinv[r] * ew[e] * g_dinv[c];
    }
}

// ---------------- helpers ----------------------------------------------------
__device__ __forceinline__ uint32_t f2tf32(float f) {
    uint32_t r;
    asm("cvt.rna.tf32.f32 %0, %1;" : "=r"(r) : "f"(f));
    return r;
}
__device__ __forceinline__ float tf32r(float f) {
    return __uint_as_float(f2tf32(f));
}

__device__ __forceinline__ void cp_async16(uint32_t smem_addr, const void* gptr,
                                           int src_bytes) {
    asm volatile("cp.async.cg.shared.global [%0], [%1], 16, %2;"
                 :: "r"(smem_addr), "l"(gptr), "r"(src_bytes));
}
__device__ __forceinline__ void cp_commit() {
    asm volatile("cp.async.commit_group;");
}
__device__ __forceinline__ void cp_wait1() {
    asm volatile("cp.async.wait_group 1;");
}

// ---------------- tf32 pre-round of weights: W -> g_wb ----------------------
__global__ void k_round(const float* __restrict__ W, int n4) {
    int i = blockIdx.x * blockDim.x + threadIdx.x;
    if (i >= n4) return;
    float4 v = ((const float4*)W)[i];
    v.x = tf32r(v.x); v.y = tf32r(v.y); v.z = tf32r(v.z); v.w = tf32r(v.w);
    ((float4*)g_wb)[i] = v;
}

// ---------------- TF32 TC GEMM, cp.async double-buffered --------------------
// C = relu(A@B + bias); A = g_a [M,K] (pre-rounded), B = g_wb [K,N]
// (pre-rounded), C = g_h. BM=128, BN=64, BK=16, 256 thr, 8 warps, 32x32 tile.
__global__ void __launch_bounds__(256)
k_gemm_tf32(const float* __restrict__ bias, int M, int K, int N) {
    __shared__ float As[2][128][20];  // [stage][m][k], stride 20 -> cf
    __shared__ float Bs[2][16][72];   // [stage][k][n], stride 72 -> cf
    const float* A = g_a;
    const float* B = g_wb;
    float* C = g_h;
    int tid = threadIdx.x;
    int lane = tid & 31, wid = tid >> 5;
    int wm = wid >> 1, wn = wid & 1;
    int bm = blockIdx.y * 128, bn = blockIdx.x * 64;

    int a_row = tid >> 1;
    int a_col0 = (tid & 1) * 8;
    int b_row = tid >> 4;
    int b_col = (tid & 15) * 4;

    const float* a_src_base = A + (size_t)(bm + a_row) * K + a_col0;
    int a_valid = (bm + a_row) < M ? 16 : 0;
    const float* b_src_base = B + (size_t)b_row * N + bn + b_col;

    uint32_t as_base = (uint32_t)__cvta_generic_to_shared(&As[0][0][0]);
    uint32_t bs_base = (uint32_t)__cvta_generic_to_shared(&Bs[0][0][0]);
    uint32_t as_stage_sz = 128 * 20 * 4;
    uint32_t bs_stage_sz = 16 * 72 * 4;

    auto load_tile = [&](int stage, int k0) {
        uint32_t ad = as_base + stage * as_stage_sz + (a_row * 20 + a_col0) * 4;
        cp_async16(ad, a_src_base + k0, a_valid);
        cp_async16(ad + 16, a_src_base + k0 + 4, a_valid);
        uint32_t bd = bs_base + stage * bs_stage_sz + (b_row * 72 + b_col) * 4;
        cp_async16(bd, b_src_base + (size_t)k0 * N, 16);
    };

    float acc[2][4][4];
#pragma unroll
    for (int i = 0; i < 2; i++)
#pragma unroll
        for (int j = 0; j < 4; j++)
#pragma unroll
            for (int r = 0; r < 4; r++) acc[i][j][r] = 0.0f;

    int nIters = K >> 4;
    load_tile(0, 0);
    cp_commit();

    for (int it = 0; it < nIters; it++) {
        if (it + 1 < nIters) load_tile((it + 1) & 1, (it + 1) << 4);
        cp_commit();
        cp_wait1();
        __syncthreads();
        int st = it & 1;

#pragma unroll
        for (int ks = 0; ks < 2; ks++) {
            int kk = ks * 8 + (lane & 3);
            uint32_t a[2][4], b[4][2];
            // inputs pre-rounded to tf32: raw bit loads, no cvt in mainloop
#pragma unroll
            for (int i = 0; i < 2; i++) {
                int m = wm * 32 + i * 16 + (lane >> 2);
                a[i][0] = __float_as_uint(As[st][m    ][kk]);
                a[i][1] = __float_as_uint(As[st][m + 8][kk]);
                a[i][2] = __float_as_uint(As[st][m    ][kk + 4]);
                a[i][3] = __float_as_uint(As[st][m + 8][kk + 4]);
            }
#pragma unroll
            for (int j = 0; j < 4; j++) {
                int nn = wn * 32 + j * 8 + (lane >> 2);
                b[j][0] = __float_as_uint(Bs[st][kk    ][nn]);
                b[j][1] = __float_as_uint(Bs[st][kk + 4][nn]);
            }
#pragma unroll
            for (int i = 0; i < 2; i++)
#pragma unroll
                for (int j = 0; j < 4; j++) {
                    asm volatile(
                        "mma.sync.aligned.m16n8k8.row.col.f32.tf32.tf32.f32 "
                        "{%0,%1,%2,%3}, {%4,%5,%6,%7}, {%8,%9}, {%0,%1,%2,%3};\n"
                        : "+f"(acc[i][j][0]), "+f"(acc[i][j][1]),
                          "+f"(acc[i][j][2]), "+f"(acc[i][j][3])
                        : "r"(a[i][0]), "r"(a[i][1]), "r"(a[i][2]), "r"(a[i][3]),
                          "r"(b[j][0]), "r"(b[j][1]));
                }
        }
        __syncthreads();
    }

    // epilogue: bias + relu
#pragma unroll
    for (int i = 0; i < 2; i++) {
#pragma unroll
        for (int j = 0; j < 4; j++) {
            int row = bm + wm * 32 + i * 16 + (lane >> 2);
            int col = bn + wn * 32 + j * 8 + (lane & 3) * 2;
            float b0 = __ldg(bias + col), b1 = __ldg(bias + col + 1);
            if (row < M) {
                float2 v0 = make_float2(fmaxf(acc[i][j][0] + b0, 0.f),
                                        fmaxf(acc[i][j][1] + b1, 0.f));
                *(float2*)(C + (size_t)row * N + col) = v0;
            }
            if (row + 8 < M) {
                float2 v1 = make_float2(fmaxf(acc[i][j][2] + b0, 0.f),
                                        fmaxf(acc[i][j][3] + b1, 0.f));
                *(float2*)(C + (size_t)(row + 8) * N + col) = v1;
            }
        }
    }
}

// ---------------- skinny GEMM for N=8: warp per row -------------------------
__global__ void k_gemm8(const float* __restrict__ W, int M, int K) {
    int gw = (blockIdx.x * blockDim.x + threadIdx.x) >> 5;
    int lane = threadIdx.x & 31;
    if (gw >= M) return;
    float acc[8] = {0.f, 0.f, 0.f, 0.f, 0.f, 0.f, 0.f, 0.f};
    const float* a = g_h + (size_t)gw * K;
    for (int k = lane; k < K; k += 32) {
        float av = a[k];
        float4 w0 = *(const float4*)(W + (size_t)k * 8);
        float4 w1 = *(const float4*)(W + (size_t)k * 8 + 4);
        acc[0] += av * w0.x; acc[1] += av * w0.y;
        acc[2] += av * w0.z; acc[3] += av * w0.w;
        acc[4] += av * w1.x; acc[5] += av * w1.y;
        acc[6] += av * w1.z; acc[7] += av * w1.w;
    }
#pragma unroll
    for (int f = 0; f < 8; f++)
#pragma unroll
        for (int o = 16; o > 0; o >>= 1)
            acc[f] += __shfl_down_sync(0xffffffffu, acc[f], o);
    if (lane == 0) {
#pragma unroll
        for (int f = 0; f < 8; f++) g_o8[(size_t)gw * 8 + f] = acc[f];
    }
}

// ---------------- aggregation (pre-GEMM): warp per node, x2 unroll ----------
// Stores tf32-rounded values (g_a feeds only the tf32 GEMM).
template <int F, int ASRC>
__global__ void __launch_bounds__(256)
k_agg(const float* __restrict__ Xext, int n) {
    int gw = (blockIdx.x * blockDim.x + threadIdx.x) >> 5;
    int lane = threadIdx.x & 31;
    if (gw >= n) return;
    const float* X = (ASRC == 0) ? Xext : (const float*)g_h;
    constexpr int NV = F / 128;
    float4 acc[NV];
    float dv = g_dinv[gw];
    float sw = dv * dv;
    const float4* xr = (const float4*)(X + (size_t)gw * F);
#pragma unroll
    for (int i = 0; i < NV; i++) {
        float4 v = xr[lane + 32 * i];
        acc[i] = make_float4(v.x * sw, v.y * sw, v.z * sw, v.w * sw);
    }
    int s = g_off[gw], e = g_off[gw + 1];
    int j = s;
    for (; j + 1 < e; j += 2) {
        int s0 = g_src[j], s1 = g_src[j + 1];
        float w0 = g_wgt[j], w1 = g_wgt[j + 1];
        const float4* r0 = (const float4*)(X + (size_t)s0 * F);
        const float4* r1 = (const float4*)(X + (size_t)s1 * F);
#pragma unroll
        for (int i = 0; i < NV; i++) {
            float4 v0 = r0[lane + 32 * i];
            float4 v1 = r1[lane + 32 * i];
            acc[i].x += w0 * v0.x + w1 * v1.x;
            acc[i].y += w0 * v0.y + w1 * v1.y;
            acc[i].z += w0 * v0.z + w1 * v1.z;
            acc[i].w += w0 * v0.w + w1 * v1.w;
        }
    }
    if (j < e) {
        int s0 = g_src[j];
        float w0 = g_wgt[j];
        const float4* r0 = (const float4*)(X + (size_t)s0 * F);
#pragma unroll
        for (int i = 0; i < NV; i++) {
            float4 v0 = r0[lane + 32 * i];
            acc[i].x += w0 * v0.x;
            acc[i].y += w0 * v0.y;
            acc[i].z += w0 * v0.z;
            acc[i].w += w0 * v0.w;
        }
    }
    float4* op = (float4*)(g_a + (size_t)gw * F);
#pragma unroll
    for (int i = 0; i < NV; i++) {
        float4 o = make_float4(tf32r(acc[i].x), tf32r(acc[i].y),
                               tf32r(acc[i].z), tf32r(acc[i].w));
        op[lane + 32 * i] = o;
    }
}

// ---------------- aggregation for F=8 (+bias), writes d_out -----------------
__global__ void k_agg8(const float* __restrict__ bias, float* __restrict__ out,
                       int n) {
    int v = blockIdx.x * blockDim.x + threadIdx.x;
    if (v >= n) return;
    float dv = g_dinv[v];
    float sw = dv * dv;
    float acc[8];
    const float* xr = g_o8 + (size_t)v * 8;
#pragma unroll
    for (int f = 0; f < 8; f++) acc[f] = xr[f] * sw;
    int s = g_off[v], e = g_off[v + 1];
    for (int j = s; j < e; j++) {
        int src = g_src[j];
        float w = g_wgt[j];
        const float* r = g_o8 + (size_t)src * 8;
#pragma unroll
        for (int f = 0; f < 8; f++) acc[f] += w * r[f];
    }
#pragma unroll
    for (int f = 0; f < 8; f++) out[(size_t)v * 8 + f] = acc[f] + bias[f];
}

// ---------------- launch ----------------------------------------------------
extern "C" void kernel_launch(void* const* d_in, const int* in_sizes, int n_in,
                              void* d_out, int out_size) {
    const float* x  = (const float*)d_in[0];
    const void*  ei = d_in[1];
    const float* ew = (const float*)d_in[2];
    const float* W1 = (const float*)d_in[3];
    const float* b1 = (const float*)d_in[4];
    const float* W2 = (const float*)d_in[5];
    const float* b2 = (const float*)d_in[6];
    const float* W3 = (const float*)d_in[7];
    const float* b3 = (const float*)d_in[8];
    float* out = (float*)d_out;

    int N = in_sizes[0] / 256;
    int E = in_sizes[2];

    // ---- setup ----
    k_init_detect<<<(N + 255) / 256, 256>>>((const int*)ei, in_sizes[1], N);
    k_deg<<<(E + 255) / 256, 256>>>(ei, ew, E, N);
    k_scan<<<1, 1024>>>(N);
    k_scatter<<<(E + 255) / 256, 256>>>(ei, ew, E, N);

    // ---- layer 1: round W1; agg(x)@256 -> g_a; relu(g_a@wb+b1) -> g_h ----
    k_round<<<(256 * 512 / 4 + 255) / 256, 256>>>(W1, 256 * 512 / 4);
    k_agg<256, 0><<<(N * 32 + 255) / 256, 256>>>(x, N);
    k_gemm_tf32<<<dim3(512 / 64, (N + 127) / 128), 256>>>(b1, N, 256, 512);

    // ---- layer 2: round W2; agg(g_h)@512 -> g_a; relu(g_a@wb+b2) -> g_h ----
    k_round<<<(512 * 768 / 4 + 255) / 256, 256>>>(W2, 512 * 768 / 4);
    k_agg<512, 1><<<(N * 32 + 255) / 256, 256>>>(nullptr, N);
    k_gemm_tf32<<<dim3(768 / 64, (N + 127) / 128), 256>>>(b2, N, 512, 768);

    // ---- layer 3: g_h@W3 -> g_o8; agg + bias -> out ----
    k_gemm8<<<(N * 32 + 255) / 256, 256>>>(W3, N, 768);
    k_agg8<<<(N + 255) / 256, 256>>>(b3, out, N);
}

// round 10
// speedup vs baseline: 1.0346x; 1.0346x over previous
#include <cuda_runtime.h>
#include <cstdint>

#define NMAX 10000
#define EMAX 320000

// ---------------- scratch (static device globals; no allocation) ------------
__device__ int   g_is64;
__device__ float g_dinv[NMAX];
__device__ int   g_cnt[NMAX];
__device__ int   g_off[NMAX + 1];
__device__ int   g_cur[NMAX];
__device__ int   g_src[EMAX];
__device__ float g_wgt[EMAX];
__device__ float g_a [(size_t)NMAX * 512];  // aggregation output (pre-GEMM)
__device__ float g_h [(size_t)NMAX * 768];  // layer activation (post-GEMM)
__device__ float g_o8[(size_t)NMAX * 8];    // layer-3 GEMM output

// ---------------- fused init + dtype detect ---------------------------------
__global__ void k_init_detect(const int* __restrict__ ei32, int nwords, int n) {
    int i = blockIdx.x * blockDim.x + threadIdx.x;
    if (i < n) { g_dinv[i] = 0.0f; g_cnt[i] = 0; }
    if (blockIdx.x == 0) {
        __shared__ int any_nonzero;
        if (threadIdx.x == 0) any_nonzero = 0;
        __syncthreads();
        int lim = nwords < 2048 ? nwords : 2048;
        for (int w = threadIdx.x * 2 + 1; w < lim; w += 512)
            if (ei32[w] != 0) atomicOr(&any_nonzero, 1);
        __syncthreads();
        if (threadIdx.x == 0) g_is64 = any_nonzero ? 0 : 1;
    }
}

__device__ __forceinline__ int load_idx(const void* ei, long long pos, int n) {
    int v = g_is64 ? (int)((const long long*)ei)[pos]
                   : ((const int*)ei)[pos];
    v = v < 0 ? 0 : (v >= n ? n - 1 : v);
    return v;
}

__global__ void k_deg(const void* __restrict__ ei,
                      const float* __restrict__ ew, int E, int n) {
    int e = blockIdx.x * blockDim.x + threadIdx.x;
    if (e >= E) return;
    int c = load_idx(ei, (long long)E + e, n);
    atomicAdd(&g_dinv[c], ew[e]);
    atomicAdd(&g_cnt[c], 1);
}

// scan (single block) + fold in dinv computation
__global__ void k_scan(int n) {
    __shared__ int part[1024];
    int t = threadIdx.x;
    for (int i = t; i < n; i += 1024)
        g_dinv[i] = rsqrtf(g_dinv[i] + 1.0f);
    int per = (n + 1023) / 1024;
    int base = t * per;
    int s = 0;
    for (int i = 0; i < per; i++) {
        int idx = base + i;
        if (idx < n) s += g_cnt[idx];
    }
    part[t] = s;
    __syncthreads();
    for (int d = 1; d < 1024; d <<= 1) {
        int v = (t >= d) ? part[t - d] : 0;
        __syncthreads();
        part[t] += v;
        __syncthreads();
    }
    int run = (t == 0) ? 0 : part[t - 1];
    for (int i = 0; i < per; i++) {
        int idx = base + i;
        if (idx < n) {
            g_off[idx] = run;
            g_cur[idx] = run;
            run += g_cnt[idx];
        }
    }
    if (t == 1023) g_off[n] = part[1023];
}

__global__ void k_scatter(const void* __restrict__ ei,
                          const float* __restrict__ ew, int E, int n) {
    int e = blockIdx.x * blockDim.x + threadIdx.x;
    if (e >= E) return;
    int r = load_idx(ei, e, n);
    int c = load_idx(ei, (long long)E + e, n);
    int p = atomicAdd(&g_cur[c], 1);
    if (p < EMAX) {
        g_src[p] = r;
        g_wgt[p] = g_dinv[r] * ew[e] * g_dinv[c];
    }
}

// ---------------- helpers ----------------------------------------------------
__device__ __forceinline__ uint32_t f2tf32(float f) {
    uint32_t r;
    asm("cvt.rna.tf32.f32 %0, %1;" : "=r"(r) : "f"(f));
    return r;
}

__device__ __forceinline__ void cp_async16(uint32_t smem_addr, const void* gptr,
                                           int src_bytes) {
    asm volatile("cp.async.cg.shared.global [%0], [%1], 16, %2;"
                 :: "r"(smem_addr), "l"(gptr), "r"(src_bytes));
}
__device__ __forceinline__ void cp_commit() {
    asm volatile("cp.async.commit_group;");
}
__device__ __forceinline__ void cp_wait1() {
    asm volatile("cp.async.wait_group 1;");
}

// ---------------- TF32 TC GEMM, cp.async 3-stage pipeline -------------------
// C = relu(A@B + bias); A = g_a [M,K], B [K,N], C = g_h.
// BM=128, BN=64, BK=16, 256 threads, 8 warps (4x2), 32x32 warp tile.
// ONE __syncthreads per iteration (3 buffers, 2 groups in flight).
__global__ void __launch_bounds__(256)
k_gemm_tf32(const float* __restrict__ B, const float* __restrict__ bias,
            int M, int K, int N) {
    __shared__ float As[3][128][20];  // [stage][m][k], stride 20 -> cf
    __shared__ float Bs[3][16][72];   // [stage][k][n], stride 72 -> cf
    const float* A = g_a;
    float* C = g_h;
    int tid = threadIdx.x;
    int lane = tid & 31, wid = tid >> 5;
    int wm = wid >> 1, wn = wid & 1;
    int bm = blockIdx.y * 128, bn = blockIdx.x * 64;

    int a_row = tid >> 1;
    int a_col0 = (tid & 1) * 8;
    int b_row = tid >> 4;
    int b_col = (tid & 15) * 4;

    const float* a_src_base = A + (size_t)(bm + a_row) * K + a_col0;
    int a_valid = (bm + a_row) < M ? 16 : 0;
    const float* b_src_base = B + (size_t)b_row * N + bn + b_col;

    uint32_t as_base = (uint32_t)__cvta_generic_to_shared(&As[0][0][0]);
    uint32_t bs_base = (uint32_t)__cvta_generic_to_shared(&Bs[0][0][0]);
    uint32_t as_stage_sz = 128 * 20 * 4;
    uint32_t bs_stage_sz = 16 * 72 * 4;

    auto load_tile = [&](int stage, int k0) {
        uint32_t ad = as_base + stage * as_stage_sz + (a_row * 20 + a_col0) * 4;
        cp_async16(ad, a_src_base + k0, a_valid);
        cp_async16(ad + 16, a_src_base + k0 + 4, a_valid);
        uint32_t bd = bs_base + stage * bs_stage_sz + (b_row * 72 + b_col) * 4;
        cp_async16(bd, b_src_base + (size_t)k0 * N, 16);
    };

    float acc[2][4][4];
#pragma unroll
    for (int i = 0; i < 2; i++)
#pragma unroll
        for (int j = 0; j < 4; j++)
#pragma unroll
            for (int r = 0; r < 4; r++) acc[i][j][r] = 0.0f;

    int nIters = K >> 4;
    load_tile(0, 0);
    cp_commit();
    if (nIters > 1) load_tile(1, 16);
    cp_commit();

    int st = 0;       // stage being computed
    int ld = 2;       // stage to load next
    for (int it = 0; it < nIters; it++) {
        cp_wait1();
        __syncthreads();

#pragma unroll
        for (int ks = 0; ks < 2; ks++) {
            int kk = ks * 8 + (lane & 3);
            uint32_t a[2][4], b[4][2];
#pragma unroll
            for (int i = 0; i < 2; i++) {
                int m = wm * 32 + i * 16 + (lane >> 2);
                a[i][0] = f2tf32(As[st][m    ][kk]);
                a[i][1] = f2tf32(As[st][m + 8][kk]);
                a[i][2] = f2tf32(As[st][m    ][kk + 4]);
                a[i][3] = f2tf32(As[st][m + 8][kk + 4]);
            }
#pragma unroll
            for (int j = 0; j < 4; j++) {
                int nn = wn * 32 + j * 8 + (lane >> 2);
                b[j][0] = f2tf32(Bs[st][kk    ][nn]);
                b[j][1] = f2tf32(Bs[st][kk + 4][nn]);
            }
#pragma unroll
            for (int i = 0; i < 2; i++)
#pragma unroll
                for (int j = 0; j < 4; j++) {
                    asm volatile(
                        "mma.sync.aligned.m16n8k8.row.col.f32.tf32.tf32.f32 "
                        "{%0,%1,%2,%3}, {%4,%5,%6,%7}, {%8,%9}, {%0,%1,%2,%3};\n"
                        : "+f"(acc[i][j][0]), "+f"(acc[i][j][1]),
                          "+f"(acc[i][j][2]), "+f"(acc[i][j][3])
                        : "r"(a[i][0]), "r"(a[i][1]), "r"(a[i][2]), "r"(a[i][3]),
                          "r"(b[j][0]), "r"(b[j][1]));
                }
        }

        // prefetch stage ld (write-safe: last read in iteration it-1,
        // all warps passed this iteration's barrier since then)
        if (it + 2 < nIters) load_tile(ld, (it + 2) << 4);
        cp_commit();  // unconditional: keeps wait_group accounting correct
        st = (st == 2) ? 0 : st + 1;
        ld = (ld == 2) ? 0 : ld + 1;
    }

    // epilogue: bias + relu
#pragma unroll
    for (int i = 0; i < 2; i++) {
#pragma unroll
        for (int j = 0; j < 4; j++) {
            int row = bm + wm * 32 + i * 16 + (lane >> 2);
            int col = bn + wn * 32 + j * 8 + (lane & 3) * 2;
            float b0 = __ldg(bias + col), b1 = __ldg(bias + col + 1);
            if (row < M) {
                float2 v0 = make_float2(fmaxf(acc[i][j][0] + b0, 0.f),
                                        fmaxf(acc[i][j][1] + b1, 0.f));
                *(float2*)(C + (size_t)row * N + col) = v0;
            }
            if (row + 8 < M) {
                float2 v1 = make_float2(fmaxf(acc[i][j][2] + b0, 0.f),
                                        fmaxf(acc[i][j][3] + b1, 0.f));
                *(float2*)(C + (size_t)(row + 8) * N + col) = v1;
            }
        }
    }
}

// ---------------- skinny GEMM for N=8: warp per row -------------------------
__global__ void k_gemm8(const float* __restrict__ W, int M, int K) {
    int gw = (blockIdx.x * blockDim.x + threadIdx.x) >> 5;
    int lane = threadIdx.x & 31;
    if (gw >= M) return;
    float acc[8] = {0.f, 0.f, 0.f, 0.f, 0.f, 0.f, 0.f, 0.f};
    const float* a = g_h + (size_t)gw * K;
    for (int k = lane; k < K; k += 32) {
        float av = a[k];
        float4 w0 = *(const float4*)(W + (size_t)k * 8);
        float4 w1 = *(const float4*)(W + (size_t)k * 8 + 4);
        acc[0] += av * w0.x; acc[1] += av * w0.y;
        acc[2] += av * w0.z; acc[3] += av * w0.w;
        acc[4] += av * w1.x; acc[5] += av * w1.y;
        acc[6] += av * w1.z; acc[7] += av * w1.w;
    }
#pragma unroll
    for (int f = 0; f < 8; f++)
#pragma unroll
        for (int o = 16; o > 0; o >>= 1)
            acc[f] += __shfl_down_sync(0xffffffffu, acc[f], o);
    if (lane == 0) {
#pragma unroll
        for (int f = 0; f < 8; f++) g_o8[(size_t)gw * 8 + f] = acc[f];
    }
}

// ---------------- aggregation (pre-GEMM): warp per node ---------------------
// unroll 4 for F=256 (NV=2), unroll 2 for F=512 (NV=4)
template <int F, int ASRC>
__global__ void __launch_bounds__(256)
k_agg(const float* __restrict__ Xext, int n) {
    int gw = (blockIdx.x * blockDim.x + threadIdx.x) >> 5;
    int lane = threadIdx.x & 31;
    if (gw >= n) return;
    const float* X = (ASRC == 0) ? Xext : (const float*)g_h;
    constexpr int NV = F / 128;
    constexpr int UN = (F == 256) ? 4 : 2;
    float4 acc[NV];
    float dv = g_dinv[gw];
    float sw = dv * dv;
    const float4* xr = (const float4*)(X + (size_t)gw * F);
#pragma unroll
    for (int i = 0; i < NV; i++) {
        float4 v = xr[lane + 32 * i];
        acc[i] = make_float4(v.x * sw, v.y * sw, v.z * sw, v.w * sw);
    }
    int s = g_off[gw], e = g_off[gw + 1];
    int j = s;
    for (; j + UN <= e; j += UN) {
        const float4* rp[UN];
        float wv[UN];
#pragma unroll
        for (int u = 0; u < UN; u++) {
            rp[u] = (const float4*)(X + (size_t)g_src[j + u] * F);
            wv[u] = g_wgt[j + u];
        }
#pragma unroll
        for (int i = 0; i < NV; i++) {
            float4 vs[UN];
#pragma unroll
            for (int u = 0; u < UN; u++) vs[u] = rp[u][lane + 32 * i];
#pragma unroll
            for (int u = 0; u < UN; u++) {
                acc[i].x += wv[u] * vs[u].x;
                acc[i].y += wv[u] * vs[u].y;
                acc[i].z += wv[u] * vs[u].z;
                acc[i].w += wv[u] * vs[u].w;
            }
        }
    }
    for (; j < e; j++) {
        int s0 = g_src[j];
        float w0 = g_wgt[j];
        const float4* r0 = (const float4*)(X + (size_t)s0 * F);
#pragma unroll
        for (int i = 0; i < NV; i++) {
            float4 v0 = r0[lane + 32 * i];
            acc[i].x += w0 * v0.x;
            acc[i].y += w0 * v0.y;
            acc[i].z += w0 * v0.z;
            acc[i].w += w0 * v0.w;
        }
    }
    float4* op = (float4*)(g_a + (size_t)gw * F);
#pragma unroll
    for (int i = 0; i < NV; i++) op[lane + 32 * i] = acc[i];
}

// ---------------- aggregation for F=8 (+bias), writes d_out -----------------
__global__ void k_agg8(const float* __restrict__ bias, float* __restrict__ out,
                       int n) {
    int v = blockIdx.x * blockDim.x + threadIdx.x;
    if (v >= n) return;
    float dv = g_dinv[v];
    float sw = dv * dv;
    float acc[8];
    const float* xr = g_o8 + (size_t)v * 8;
#pragma unroll
    for (int f = 0; f < 8; f++) acc[f] = xr[f] * sw;
    int s = g_off[v], e = g_off[v + 1];
    for (int j = s; j < e; j++) {
        int src = g_src[j];
        float w = g_wgt[j];
        const float* r = g_o8 + (size_t)src * 8;
#pragma unroll
        for (int f = 0; f < 8; f++) acc[f] += w * r[f];
    }
#pragma unroll
    for (int f = 0; f < 8; f++) out[(size_t)v * 8 + f] = acc[f] + bias[f];
}

// ---------------- launch ----------------------------------------------------
extern "C" void kernel_launch(void* const* d_in, const int* in_sizes, int n_in,
                              void* d_out, int out_size) {
    const float* x  = (const float*)d_in[0];
    const void*  ei = d_in[1];
    const float* ew = (const float*)d_in[2];
    const float* W1 = (const float*)d_in[3];
    const float* b1 = (const float*)d_in[4];
    const float* W2 = (const float*)d_in[5];
    const float* b2 = (const float*)d_in[6];
    const float* W3 = (const float*)d_in[7];
    const float* b3 = (const float*)d_in[8];
    float* out = (float*)d_out;

    int N = in_sizes[0] / 256;
    int E = in_sizes[2];

    // ---- setup ----
    k_init_detect<<<(N + 255) / 256, 256>>>((const int*)ei, in_sizes[1], N);
    k_deg<<<(E + 255) / 256, 256>>>(ei, ew, E, N);
    k_scan<<<1, 1024>>>(N);
    k_scatter<<<(E + 255) / 256, 256>>>(ei, ew, E, N);

    // ---- layer 1: agg(x)@256 -> g_a; relu(g_a@W1+b1) -> g_h ----
    k_agg<256, 0><<<(N * 32 + 255) / 256, 256>>>(x, N);
    k_gemm_tf32<<<dim3(512 / 64, (N + 127) / 128), 256>>>(W1, b1, N, 256, 512);

    // ---- layer 2: agg(g_h)@512 -> g_a; relu(g_a@W2+b2) -> g_h ----
    k_agg<512, 1><<<(N * 32 + 255) / 256, 256>>>(nullptr, N);
    k_gemm_tf32<<<dim3(768 / 64, (N + 127) / 128), 256>>>(W2, b2, N, 512, 768);

    // ---- layer 3: g_h@W3 -> g_o8; agg + bias -> out ----
    k_gemm8<<<(N * 32 + 255) / 256, 256>>>(W3, N, 768);
    k_agg8<<<(N + 255) / 256, 256>>>(b3, out, N);
}

// round 11
// speedup vs baseline: 1.1076x; 1.0705x over previous
#include <cuda_runtime.h>
#include <cstdint>

#define NMAX 10000
#define EMAX 320000
#define BCAP 128   // bucket capacity per node (P(deg>128) ~ 0 for Poisson(32))

// ---------------- scratch (static device globals; no allocation) ------------
__device__ int       g_is64;
__device__ float     g_deg[NMAX];                     // weighted degree (raw)
__device__ int       g_cnt[NMAX];                     // per-target edge count
__device__ unsigned long long g_ebuf[(size_t)NMAX * BCAP]; // packed (ew,src)
__device__ float g_a [(size_t)NMAX * 512];  // aggregation output (pre-GEMM)
__device__ float g_h [(size_t)NMAX * 768];  // layer activation (post-GEMM)
__device__ float g_o8[(size_t)NMAX * 8];    // layer-3 GEMM output

// ---------------- fused init + dtype detect ---------------------------------
__global__ void k_init_detect(const int* __restrict__ ei32, int nwords, int n) {
    int i = blockIdx.x * blockDim.x + threadIdx.x;
    if (i < n) { g_deg[i] = 0.0f; g_cnt[i] = 0; }
    if (blockIdx.x == 0) {
        __shared__ int any_nonzero;
        if (threadIdx.x == 0) any_nonzero = 0;
        __syncthreads();
        int lim = nwords < 2048 ? nwords : 2048;
        for (int w = threadIdx.x * 2 + 1; w < lim; w += 512)
            if (ei32[w] != 0) atomicOr(&any_nonzero, 1);
        __syncthreads();
        if (threadIdx.x == 0) g_is64 = any_nonzero ? 0 : 1;
    }
}

__device__ __forceinline__ int load_idx(const void* ei, long long pos, int n) {
    int v = g_is64 ? (int)((const long long*)ei)[pos]
                   : ((const int*)ei)[pos];
    v = v < 0 ? 0 : (v >= n ? n - 1 : v);
    return v;
}

// ---------------- single edge pass: degree + bucket scatter ------------------
__global__ void k_pass1(const void* __restrict__ ei,
                        const float* __restrict__ ew, int E, int n) {
    int e = blockIdx.x * blockDim.x + threadIdx.x;
    if (e >= E) return;
    int r = load_idx(ei, e, n);
    int c = load_idx(ei, (long long)E + e, n);
    float w = ew[e];
    atomicAdd(&g_deg[c], w);
    int p = atomicAdd(&g_cnt[c], 1);
    if (p < BCAP) {
        unsigned long long packed =
            ((unsigned long long)__float_as_uint(w) << 32) | (unsigned)r;
        g_ebuf[(size_t)c * BCAP + p] = packed;
    }
}

// ---------------- helpers ----------------------------------------------------
__device__ __forceinline__ uint32_t f2tf32(float f) {
    uint32_t r;
    asm("cvt.rna.tf32.f32 %0, %1;" : "=r"(r) : "f"(f));
    return r;
}

__device__ __forceinline__ void cp_async16(uint32_t smem_addr, const void* gptr,
                                           int src_bytes) {
    asm volatile("cp.async.cg.shared.global [%0], [%1], 16, %2;"
                 :: "r"(smem_addr), "l"(gptr), "r"(src_bytes));
}
__device__ __forceinline__ void cp_commit() {
    asm volatile("cp.async.commit_group;");
}
__device__ __forceinline__ void cp_wait1() {
    asm volatile("cp.async.wait_group 1;");
}

// ---------------- TF32 TC GEMM, cp.async 3-stage pipeline -------------------
// C = relu(A@B + bias); A = g_a [M,K], B [K,N], C = g_h.
// BM=128, BN=64, BK=16, 256 threads, 8 warps (4x2), 32x32 warp tile.
__global__ void __launch_bounds__(256)
k_gemm_tf32(const float* __restrict__ B, const float* __restrict__ bias,
            int M, int K, int N) {
    __shared__ float As[3][128][20];
    __shared__ float Bs[3][16][72];
    const float* A = g_a;
    float* C = g_h;
    int tid = threadIdx.x;
    int lane = tid & 31, wid = tid >> 5;
    int wm = wid >> 1, wn = wid & 1;
    int bm = blockIdx.y * 128, bn = blockIdx.x * 64;

    int a_row = tid >> 1;
    int a_col0 = (tid & 1) * 8;
    int b_row = tid >> 4;
    int b_col = (tid & 15) * 4;

    const float* a_src_base = A + (size_t)(bm + a_row) * K + a_col0;
    int a_valid = (bm + a_row) < M ? 16 : 0;
    const float* b_src_base = B + (size_t)b_row * N + bn + b_col;

    uint32_t as_base = (uint32_t)__cvta_generic_to_shared(&As[0][0][0]);
    uint32_t bs_base = (uint32_t)__cvta_generic_to_shared(&Bs[0][0][0]);
    uint32_t as_stage_sz = 128 * 20 * 4;
    uint32_t bs_stage_sz = 16 * 72 * 4;

    auto load_tile = [&](int stage, int k0) {
        uint32_t ad = as_base + stage * as_stage_sz + (a_row * 20 + a_col0) * 4;
        cp_async16(ad, a_src_base + k0, a_valid);
        cp_async16(ad + 16, a_src_base + k0 + 4, a_valid);
        uint32_t bd = bs_base + stage * bs_stage_sz + (b_row * 72 + b_col) * 4;
        cp_async16(bd, b_src_base + (size_t)k0 * N, 16);
    };

    float acc[2][4][4];
#pragma unroll
    for (int i = 0; i < 2; i++)
#pragma unroll
        for (int j = 0; j < 4; j++)
#pragma unroll
            for (int r = 0; r < 4; r++) acc[i][j][r] = 0.0f;

    int nIters = K >> 4;
    load_tile(0, 0);
    cp_commit();
    if (nIters > 1) load_tile(1, 16);
    cp_commit();

    int st = 0, ld = 2;
    for (int it = 0; it < nIters; it++) {
        cp_wait1();
        __syncthreads();

#pragma unroll
        for (int ks = 0; ks < 2; ks++) {
            int kk = ks * 8 + (lane & 3);
            uint32_t a[2][4], b[4][2];
#pragma unroll
            for (int i = 0; i < 2; i++) {
                int m = wm * 32 + i * 16 + (lane >> 2);
                a[i][0] = f2tf32(As[st][m    ][kk]);
                a[i][1] = f2tf32(As[st][m + 8][kk]);
                a[i][2] = f2tf32(As[st][m    ][kk + 4]);
                a[i][3] = f2tf32(As[st][m + 8][kk + 4]);
            }
#pragma unroll
            for (int j = 0; j < 4; j++) {
                int nn = wn * 32 + j * 8 + (lane >> 2);
                b[j][0] = f2tf32(Bs[st][kk    ][nn]);
                b[j][1] = f2tf32(Bs[st][kk + 4][nn]);
            }
#pragma unroll
            for (int i = 0; i < 2; i++)
#pragma unroll
                for (int j = 0; j < 4; j++) {
                    asm volatile(
                        "mma.sync.aligned.m16n8k8.row.col.f32.tf32.tf32.f32 "
                        "{%0,%1,%2,%3}, {%4,%5,%6,%7}, {%8,%9}, {%0,%1,%2,%3};\n"
                        : "+f"(acc[i][j][0]), "+f"(acc[i][j][1]),
                          "+f"(acc[i][j][2]), "+f"(acc[i][j][3])
                        : "r"(a[i][0]), "r"(a[i][1]), "r"(a[i][2]), "r"(a[i][3]),
                          "r"(b[j][0]), "r"(b[j][1]));
                }
        }

        if (it + 2 < nIters) load_tile(ld, (it + 2) << 4);
        cp_commit();
        st = (st == 2) ? 0 : st + 1;
        ld = (ld == 2) ? 0 : ld + 1;
    }

#pragma unroll
    for (int i = 0; i < 2; i++) {
#pragma unroll
        for (int j = 0; j < 4; j++) {
            int row = bm + wm * 32 + i * 16 + (lane >> 2);
            int col = bn + wn * 32 + j * 8 + (lane & 3) * 2;
            float b0 = __ldg(bias + col), b1 = __ldg(bias + col + 1);
            if (row < M) {
                float2 v0 = make_float2(fmaxf(acc[i][j][0] + b0, 0.f),
                                        fmaxf(acc[i][j][1] + b1, 0.f));
                *(float2*)(C + (size_t)row * N + col) = v0;
            }
            if (row + 8 < M) {
                float2 v1 = make_float2(fmaxf(acc[i][j][2] + b0, 0.f),
                                        fmaxf(acc[i][j][3] + b1, 0.f));
                *(float2*)(C + (size_t)(row + 8) * N + col) = v1;
            }
        }
    }
}

// ---------------- skinny GEMM N=8: W3 in SMEM, warp handles 4 rows ----------
__global__ void __launch_bounds__(256)
k_gemm8(const float* __restrict__ W, int M, int K) {
    __shared__ float Ws[768 * 8];  // 24 KB
    int tid = threadIdx.x;
    // cooperative load of W3 (K*8 floats)
    for (int i = tid; i < K * 2; i += 256)
        ((float4*)Ws)[i] = ((const float4*)W)[i];
    __syncthreads();

    int wid = tid >> 5, lane = tid & 31;
    int base = (blockIdx.x * 8 + wid) * 4;  // 4 nodes per warp
    if (base >= M) return;
    int nr = (M - base < 4) ? (M - base) : 4;

    float acc[4][8];
#pragma unroll
    for (int r = 0; r < 4; r++)
#pragma unroll
        for (int f = 0; f < 8; f++) acc[r][f] = 0.0f;

    const float* a0 = g_h + (size_t)base * K;
    for (int k = lane; k < K; k += 32) {
        float4 w0 = *(const float4*)(Ws + k * 8);
        float4 w1 = *(const float4*)(Ws + k * 8 + 4);
        float av[4];
#pragma unroll
        for (int r = 0; r < 4; r++)
            av[r] = (r < nr) ? a0[(size_t)r * K + k] : 0.0f;
#pragma unroll
        for (int r = 0; r < 4; r++) {
            acc[r][0] += av[r] * w0.x; acc[r][1] += av[r] * w0.y;
            acc[r][2] += av[r] * w0.z; acc[r][3] += av[r] * w0.w;
            acc[r][4] += av[r] * w1.x; acc[r][5] += av[r] * w1.y;
            acc[r][6] += av[r] * w1.z; acc[r][7] += av[r] * w1.w;
        }
    }
#pragma unroll
    for (int r = 0; r < 4; r++)
#pragma unroll
        for (int f = 0; f < 8; f++)
#pragma unroll
            for (int o = 16; o > 0; o >>= 1)
                acc[r][f] += __shfl_down_sync(0xffffffffu, acc[r][f], o);
    if (lane == 0) {
#pragma unroll
        for (int r = 0; r < 4; r++)
            if (r < nr)
#pragma unroll
                for (int f = 0; f < 8; f++)
                    g_o8[(size_t)(base + r) * 8 + f] = acc[r][f];
    }
}

// ---------------- aggregation (pre-GEMM): warp per node, bucket edges -------
// out[v] = dv*( Σ_e ew*rsqrt(deg[src]+1)*X[src] ) + dv^2*X[v], dv=rsqrt(deg[v]+1)
template <int F, int ASRC>
__global__ void __launch_bounds__(256)
k_agg(const float* __restrict__ Xext, int n) {
    int gw = (blockIdx.x * blockDim.x + threadIdx.x) >> 5;
    int lane = threadIdx.x & 31;
    if (gw >= n) return;
    const float* X = (ASRC == 0) ? Xext : (const float*)g_h;
    constexpr int NV = F / 128;
    constexpr int UN = (F == 256) ? 4 : 2;
    float dv = rsqrtf(g_deg[gw] + 1.0f);
    float4 acc[NV];
    const float4* xr = (const float4*)(X + (size_t)gw * F);
#pragma unroll
    for (int i = 0; i < NV; i++) {
        float4 v = xr[lane + 32 * i];
        acc[i] = make_float4(v.x * dv, v.y * dv, v.z * dv, v.w * dv);
    }
    int cnt = g_cnt[gw];
    cnt = cnt > BCAP ? BCAP : cnt;
    const unsigned long long* eb = g_ebuf + (size_t)gw * BCAP;
    int j = 0;
    for (; j + UN <= cnt; j += UN) {
        const float4* rp[UN];
        float wv[UN];
#pragma unroll
        for (int u = 0; u < UN; u++) {
            unsigned long long p = eb[j + u];
            int src = (int)(unsigned)p;
            float w = __uint_as_float((unsigned)(p >> 32));
            wv[u] = w * rsqrtf(g_deg[src] + 1.0f);
            rp[u] = (const float4*)(X + (size_t)src * F);
        }
#pragma unroll
        for (int i = 0; i < NV; i++) {
            float4 vs[UN];
#pragma unroll
            for (int u = 0; u < UN; u++) vs[u] = rp[u][lane + 32 * i];
#pragma unroll
            for (int u = 0; u < UN; u++) {
                acc[i].x += wv[u] * vs[u].x;
                acc[i].y += wv[u] * vs[u].y;
                acc[i].z += wv[u] * vs[u].z;
                acc[i].w += wv[u] * vs[u].w;
            }
        }
    }
    for (; j < cnt; j++) {
        unsigned long long p = eb[j];
        int src = (int)(unsigned)p;
        float w0 = __uint_as_float((unsigned)(p >> 32)) * rsqrtf(g_deg[src] + 1.0f);
        const float4* r0 = (const float4*)(X + (size_t)src * F);
#pragma unroll
        for (int i = 0; i < NV; i++) {
            float4 v0 = r0[lane + 32 * i];
            acc[i].x += w0 * v0.x;
            acc[i].y += w0 * v0.y;
            acc[i].z += w0 * v0.z;
            acc[i].w += w0 * v0.w;
        }
    }
    float4* op = (float4*)(g_a + (size_t)gw * F);
#pragma unroll
    for (int i = 0; i < NV; i++) {
        float4 o = make_float4(acc[i].x * dv, acc[i].y * dv,
                               acc[i].z * dv, acc[i].w * dv);
        op[lane + 32 * i] = o;
    }
}

// ---------------- aggregation F=8 (+bias), writes d_out ---------------------
__global__ void k_agg8(const float* __restrict__ bias, float* __restrict__ out,
                       int n) {
    int v = blockIdx.x * blockDim.x + threadIdx.x;
    if (v >= n) return;
    float dv = rsqrtf(g_deg[v] + 1.0f);
    float acc[8];
    const float* xr = g_o8 + (size_t)v * 8;
#pragma unroll
    for (int f = 0; f < 8; f++) acc[f] = xr[f] * dv;
    int cnt = g_cnt[v];
    cnt = cnt > BCAP ? BCAP : cnt;
    const unsigned long long* eb = g_ebuf + (size_t)v * BCAP;
    for (int j = 0; j < cnt; j++) {
        unsigned long long p = eb[j];
        int src = (int)(unsigned)p;
        float w = __uint_as_float((unsigned)(p >> 32)) * rsqrtf(g_deg[src] + 1.0f);
        const float* r = g_o8 + (size_t)src * 8;
#pragma unroll
        for (int f = 0; f < 8; f++) acc[f] += w * r[f];
    }
#pragma unroll
    for (int f = 0; f < 8; f++) out[(size_t)v * 8 + f] = acc[f] * dv + bias[f];
}

// ---------------- launch ----------------------------------------------------
extern "C" void kernel_launch(void* const* d_in, const int* in_sizes, int n_in,
                              void* d_out, int out_size) {
    const float* x  = (const float*)d_in[0];
    const void*  ei = d_in[1];
    const float* ew = (const float*)d_in[2];
    const float* W1 = (const float*)d_in[3];
    const float* b1 = (const float*)d_in[4];
    const float* W2 = (const float*)d_in[5];
    const float* b2 = (const float*)d_in[6];
    const float* W3 = (const float*)d_in[7];
    const float* b3 = (const float*)d_in[8];
    float* out = (float*)d_out;

    int N = in_sizes[0] / 256;
    int E = in_sizes[2];

    // ---- setup: 2 kernels ----
    k_init_detect<<<(N + 255) / 256, 256>>>((const int*)ei, in_sizes[1], N);
    k_pass1<<<(E + 255) / 256, 256>>>(ei, ew, E, N);

    // ---- layer 1: agg(x)@256 -> g_a; relu(g_a@W1+b1) -> g_h ----
    k_agg<256, 0><<<(N * 32 + 255) / 256, 256>>>(x, N);
    k_gemm_tf32<<<dim3(512 / 64, (N + 127) / 128), 256>>>(W1, b1, N, 256, 512);

    // ---- layer 2: agg(g_h)@512 -> g_a; relu(g_a@W2+b2) -> g_h ----
    k_agg<512, 1><<<(N * 32 + 255) / 256, 256>>>(nullptr, N);
    k_gemm_tf32<<<dim3(768 / 64, (N + 127) / 128), 256>>>(W2, b2, N, 512, 768);

    // ---- layer 3: g_h@W3 -> g_o8 (W3 in smem); agg + bias -> out ----
    k_gemm8<<<(N + 31) / 32, 256>>>(W3, N, 768);
    k_agg8<<<(N + 255) / 256, 256>>>(b3, out, N);
}

// round 13
// speedup vs baseline: 1.1128x; 1.0047x over previous
#include <cuda_runtime.h>
#include <cstdint>

#define NMAX 10000
#define EMAX 320000
#define BCAP 128
#define AGRPS 316   // ceil(10112/32): A fragment groups incl. padding

// ---------------- scratch (static device globals; no allocation) ------------
__device__ int       g_is64;
__device__ float     g_deg[NMAX];
__device__ int       g_cnt[NMAX];
__device__ unsigned long long g_ebuf[(size_t)NMAX * BCAP];
__device__ float g_a [(size_t)AGRPS * 64 * 256];  // A in fragment layout (max K8=64)
__device__ float g_h [(size_t)NMAX * 768];
__device__ float g_wb1[256 * 512];                // W1 permuted tf32
__device__ float g_wb2[512 * 768];                // W2 permuted tf32
__device__ float g_o8[(size_t)NMAX * 8];

// ---------------- fused init + dtype detect ---------------------------------
__global__ void k_init_detect(const int* __restrict__ ei32, int nwords, int n) {
    int i = blockIdx.x * blockDim.x + threadIdx.x;
    if (i < n) { g_deg[i] = 0.0f; g_cnt[i] = 0; }
    if (blockIdx.x == 0) {
        __shared__ int any_nonzero;
        if (threadIdx.x == 0) any_nonzero = 0;
        __syncthreads();
        int lim = nwords < 2048 ? nwords : 2048;
        for (int w = threadIdx.x * 2 + 1; w < lim; w += 512)
            if (ei32[w] != 0) atomicOr(&any_nonzero, 1);
        __syncthreads();
        if (threadIdx.x == 0) g_is64 = any_nonzero ? 0 : 1;
    }
}

__device__ __forceinline__ int load_idx(const void* ei, long long pos, int n) {
    int v = g_is64 ? (int)((const long long*)ei)[pos]
                   : ((const int*)ei)[pos];
    v = v < 0 ? 0 : (v >= n ? n - 1 : v);
    return v;
}

// ---------------- single edge pass: degree + bucket scatter ------------------
__global__ void k_pass1(const void* __restrict__ ei,
                        const float* __restrict__ ew, int E, int n) {
    int e = blockIdx.x * blockDim.x + threadIdx.x;
    if (e >= E) return;
    int r = load_idx(ei, e, n);
    int c = load_idx(ei, (long long)E + e, n);
    float w = ew[e];
    atomicAdd(&g_deg[c], w);
    int p = atomicAdd(&g_cnt[c], 1);
    if (p < BCAP) {
        unsigned long long packed =
            ((unsigned long long)__float_as_uint(w) << 32) | (unsigned)r;
        g_ebuf[(size_t)c * BCAP + p] = packed;
    }
}

// ---------------- helpers ----------------------------------------------------
__device__ __forceinline__ uint32_t f2tf32(float f) {
    uint32_t r;
    asm("cvt.rna.tf32.f32 %0, %1;" : "=r"(r) : "f"(f));
    return r;
}
__device__ __forceinline__ float tf32r(float f) {
    return __uint_as_float(f2tf32(f));
}
__device__ __forceinline__ void cp_async16(uint32_t smem_addr, const void* gptr) {
    asm volatile("cp.async.cg.shared.global [%0], [%1], 16;"
                 :: "r"(smem_addr), "l"(gptr));
}
__device__ __forceinline__ void cp_commit() {
    asm volatile("cp.async.commit_group;");
}
__device__ __forceinline__ void cp_wait1() {
    asm volatile("cp.async.wait_group 1;");
}

// ---------------- weight prep: permute+round W1, W2 --------------------------
// B layout: [n_grp32][k8][j4][lane32][slot2]; slot pair = (W[k][n], W[k+4][n]);
// lane = 4*(n&7) + (k&3).
__global__ void k_prep(const float* __restrict__ W1, const float* __restrict__ W2) {
    int idx = blockIdx.x * 256 + threadIdx.x;
    if (idx < 256 * 512) {
        int k = idx >> 9, n = idx & 511;           // K=256, N=512, K8=32
        float v = tf32r(W1[idx]);
        int grp = n >> 5, j = (n >> 3) & 3;
        int ln = 4 * (n & 7) + (k & 3);
        int slot = (k >> 2) & 1;
        g_wb1[((grp * 32 + (k >> 3)) * 4 + j) * 64 + ln * 2 + slot] = v;
    } else {
        int i2 = idx - 256 * 512;
        if (i2 >= 512 * 768) return;
        int k = i2 / 768, n = i2 - k * 768;        // K=512, N=768, K8=64
        float v = tf32r(W2[i2]);
        int grp = n >> 5, j = (n >> 3) & 3;
        int ln = 4 * (n & 7) + (k & 3);
        int slot = (k >> 2) & 1;
        g_wb2[((grp * 64 + (k >> 3)) * 4 + j) * 64 + ln * 2 + slot] = v;
    }
}

// ---------------- TF32 TC GEMM, fragment-layout operands --------------------
// A: g_a fragment layout (LDG.128 direct). B: g_wb1/g_wb2 via WSEL template.
// C = relu(A@B + bias) -> g_h row-major. BM=128, BN=64, BK=16, 256 threads.
template <int WSEL>
__global__ void __launch_bounds__(256)
k_gemm_tf32(const float* __restrict__ bias, int M, int K, int N) {
    __shared__ float Bs[3][1024];   // 3 stages x 4KB
    const float* Bp = (WSEL == 0) ? (const float*)g_wb1 : (const float*)g_wb2;
    int tid = threadIdx.x;
    int lane = tid & 31, wid = tid >> 5;
    int wm = wid >> 1, wn = wid & 1;
    int bm = blockIdx.y * 128;
    int K8 = K >> 3;
    int agrp = blockIdx.y * 4 + wm;

    const float4* Ap = (const float4*)g_a;
    long a_base = ((long)agrp * K8 * 2) * 32 + lane;   // float4 index

    // B staging: thread covers 16B of the 4KB stage
    int t_grp = tid >> 7;
    int t_off = (tid & 127) * 4;
    const float* b_src = Bp + ((size_t)(blockIdx.x * 2 + t_grp) * K8) * 256 + t_off;
    uint32_t bs0 = (uint32_t)__cvta_generic_to_shared(&Bs[0][0]);
    uint32_t bdst = bs0 + (t_grp * 512 + t_off) * 4;

    float acc[2][4][4];
#pragma unroll
    for (int i = 0; i < 2; i++)
#pragma unroll
        for (int j = 0; j < 4; j++)
#pragma unroll
            for (int r = 0; r < 4; r++) acc[i][j][r] = 0.0f;

    int nIters = K >> 4;
    cp_async16(bdst, b_src);
    cp_commit();
    if (nIters > 1) cp_async16(bdst + 4096, b_src + 512);
    cp_commit();

    float4 af[2][2];
#pragma unroll
    for (int ks = 0; ks < 2; ks++)
#pragma unroll
        for (int i = 0; i < 2; i++)
            af[ks][i] = Ap[a_base + ((long)ks * 2 + i) * 32];

    int st = 0, ld = 2;
    for (int it = 0; it < nIters; it++) {
        cp_wait1();
        __syncthreads();
        if (it + 2 < nIters)
            cp_async16(bs0 + ld * 4096 + (t_grp * 512 + t_off) * 4,
                       b_src + (size_t)(it + 2) * 512);
        cp_commit();

        float4 ac[2][2];
#pragma unroll
        for (int ks = 0; ks < 2; ks++)
#pragma unroll
            for (int i = 0; i < 2; i++) ac[ks][i] = af[ks][i];
        if (it + 1 < nIters) {
            long nb = a_base + (long)(it + 1) * 4 * 32;
#pragma unroll
            for (int ks = 0; ks < 2; ks++)
#pragma unroll
                for (int i = 0; i < 2; i++)
                    af[ks][i] = Ap[nb + ((long)ks * 2 + i) * 32];
        }

#pragma unroll
        for (int ks = 0; ks < 2; ks++) {
            uint32_t a[2][4];
#pragma unroll
            for (int i = 0; i < 2; i++) {
                a[i][0] = __float_as_uint(ac[ks][i].x);
                a[i][1] = __float_as_uint(ac[ks][i].y);
                a[i][2] = __float_as_uint(ac[ks][i].z);
                a[i][3] = __float_as_uint(ac[ks][i].w);
            }
            float2 b[4];
#pragma unroll
            for (int j = 0; j < 4; j++)
                b[j] = *(const float2*)&Bs[st][((wn * 2 + ks) * 4 + j) * 64 + lane * 2];
#pragma unroll
            for (int i = 0; i < 2; i++)
#pragma unroll
                for (int j = 0; j < 4; j++) {
                    asm volatile(
                        "mma.sync.aligned.m16n8k8.row.col.f32.tf32.tf32.f32 "
                        "{%0,%1,%2,%3}, {%4,%5,%6,%7}, {%8,%9}, {%0,%1,%2,%3};\n"
                        : "+f"(acc[i][j][0]), "+f"(acc[i][j][1]),
                          "+f"(acc[i][j][2]), "+f"(acc[i][j][3])
                        : "r"(a[i][0]), "r"(a[i][1]), "r"(a[i][2]), "r"(a[i][3]),
                          "r"(__float_as_uint(b[j].x)), "r"(__float_as_uint(b[j].y)));
                }
        }
        st = (st == 2) ? 0 : st + 1;
        ld = (ld == 2) ? 0 : ld + 1;
    }

    // epilogue: bias + relu -> g_h row-major
    int bn = blockIdx.x * 64;
#pragma unroll
    for (int i = 0; i < 2; i++) {
#pragma unroll
        for (int j = 0; j < 4; j++) {
            int row = bm + wm * 32 + i * 16 + (lane >> 2);
            int col = bn + wn * 32 + j * 8 + (lane & 3) * 2;
            float b0 = __ldg(bias + col), b1 = __ldg(bias + col + 1);
            if (row < M) {
                float2 v0 = make_float2(fmaxf(acc[i][j][0] + b0, 0.f),
                                        fmaxf(acc[i][j][1] + b1, 0.f));
                *(float2*)(g_h + (size_t)row * N + col) = v0;
            }
            if (row + 8 < M) {
                float2 v1 = make_float2(fmaxf(acc[i][j][2] + b0, 0.f),
                                        fmaxf(acc[i][j][3] + b1, 0.f));
                *(float2*)(g_h + (size_t)(row + 8) * N + col) = v1;
            }
        }
    }
}

// ---------------- skinny GEMM N=8: W3 in SMEM, warp handles 4 rows ----------
__global__ void __launch_bounds__(256)
k_gemm8(const float* __restrict__ W, int M, int K) {
    __shared__ float Ws[768 * 8];
    int tid = threadIdx.x;
    for (int i = tid; i < K * 2; i += 256)
        ((float4*)Ws)[i] = ((const float4*)W)[i];
    __syncthreads();

    int wid = tid >> 5, lane = tid & 31;
    int base = (blockIdx.x * 8 + wid) * 4;
    if (base >= M) return;
    int nr = (M - base < 4) ? (M - base) : 4;

    float acc[4][8];
#pragma unroll
    for (int r = 0; r < 4; r++)
#pragma unroll
        for (int f = 0; f < 8; f++) acc[r][f] = 0.0f;

    const float* a0 = g_h + (size_t)base * K;
    for (int k = lane; k < K; k += 32) {
        float4 w0 = *(const float4*)(Ws + k * 8);
        float4 w1 = *(const float4*)(Ws + k * 8 + 4);
        float av[4];
#pragma unroll
        for (int r = 0; r < 4; r++)
            av[r] = (r < nr) ? a0[(size_t)r * K + k] : 0.0f;
#pragma unroll
        for (int r = 0; r < 4; r++) {
            acc[r][0] += av[r] * w0.x; acc[r][1] += av[r] * w0.y;
            acc[r][2] += av[r] * w0.z; acc[r][3] += av[r] * w0.w;
            acc[r][4] += av[r] * w1.x; acc[r][5] += av[r] * w1.y;
            acc[r][6] += av[r] * w1.z; acc[r][7] += av[r] * w1.w;
        }
    }
#pragma unroll
    for (int r = 0; r < 4; r++)
#pragma unroll
        for (int f = 0; f < 8; f++)
#pragma unroll
            for (int o = 16; o > 0; o >>= 1)
                acc[r][f] += __shfl_down_sync(0xffffffffu, acc[r][f], o);
    if (lane == 0) {
#pragma unroll
        for (int r = 0; r < 4; r++)
            if (r < nr)
#pragma unroll
                for (int f = 0; f < 8; f++)
                    g_o8[(size_t)(base + r) * 8 + f] = acc[r][f];
    }
}

// ---------------- aggregation: warp per node -> g_a FRAGMENT layout ---------
template <int F, int ASRC>
__global__ void __launch_bounds__(256)
k_agg(const float* __restrict__ Xext, int n) {
    int gw = (blockIdx.x * blockDim.x + threadIdx.x) >> 5;
    int lane = threadIdx.x & 31;
    if (gw >= n) return;
    const float* X = (ASRC == 0) ? Xext : (const float*)g_h;
    constexpr int NV = F / 128;
    constexpr int UN = (F == 256) ? 4 : 2;
    constexpr int K8 = F / 8;
    float dv = rsqrtf(g_deg[gw] + 1.0f);
    float4 acc[NV];
    const float4* xr = (const float4*)(X + (size_t)gw * F);
#pragma unroll
    for (int i = 0; i < NV; i++) {
        float4 v = xr[lane + 32 * i];
        acc[i] = make_float4(v.x * dv, v.y * dv, v.z * dv, v.w * dv);
    }
    int cnt = g_cnt[gw];
    cnt = cnt > BCAP ? BCAP : cnt;
    const unsigned long long* eb = g_ebuf + (size_t)gw * BCAP;
    int j = 0;
    for (; j + UN <= cnt; j += UN) {
        const float4* rp[UN];
        float wv[UN];
#pragma unroll
        for (int u = 0; u < UN; u++) {
            unsigned long long p = eb[j + u];
            int src = (int)(unsigned)p;
            float w = __uint_as_float((unsigned)(p >> 32));
            wv[u] = w * rsqrtf(g_deg[src] + 1.0f);
            rp[u] = (const float4*)(X + (size_t)src * F);
        }
#pragma unroll
        for (int i = 0; i < NV; i++) {
            float4 vs[UN];
#pragma unroll
            for (int u = 0; u < UN; u++) vs[u] = rp[u][lane + 32 * i];
#pragma unroll
            for (int u = 0; u < UN; u++) {
                acc[i].x += wv[u] * vs[u].x;
                acc[i].y += wv[u] * vs[u].y;
                acc[i].z += wv[u] * vs[u].z;
                acc[i].w += wv[u] * vs[u].w;
            }
        }
    }
    for (; j < cnt; j++) {
        unsigned long long p = eb[j];
        int src = (int)(unsigned)p;
        float w0 = __uint_as_float((unsigned)(p >> 32)) * rsqrtf(g_deg[src] + 1.0f);
        const float4* r0 = (const float4*)(X + (size_t)src * F);
#pragma unroll
        for (int i = 0; i < NV; i++) {
            float4 v0 = r0[lane + 32 * i];
            acc[i].x += w0 * v0.x;
            acc[i].y += w0 * v0.y;
            acc[i].z += w0 * v0.z;
            acc[i].w += w0 * v0.w;
        }
    }
    // scatter into A fragment layout, tf32-rounded:
    // float index = ((grp*K8 + k8)*2 + i16)*128 + frag_lane*4 + slot
    // frag_lane = (r16&7)*4 + c; slot = (r16>>3) + 2*(lane&1); k8 = (lane>>1)+16q
    int grp = gw >> 5, rr = gw & 31;
    int i16 = rr >> 4, row8 = rr & 15;
    int sb = (row8 >> 3) + 2 * (lane & 1);
    int lp4 = (row8 & 7) * 16;
#pragma unroll
    for (int q = 0; q < NV; q++) {
        int k8 = (lane >> 1) + 16 * q;
        long base = ((long)(grp * K8 + k8) * 2 + i16) * 128 + lp4 + sb;
        g_a[base + 0]  = tf32r(acc[q].x * dv);
        g_a[base + 4]  = tf32r(acc[q].y * dv);
        g_a[base + 8]  = tf32r(acc[q].z * dv);
        g_a[base + 12] = tf32r(acc[q].w * dv);
    }
}

// ---------------- aggregation F=8 (+bias), writes d_out ---------------------
__global__ void k_agg8(const float* __restrict__ bias, float* __restrict__ out,
                       int n) {
    int v = blockIdx.x * blockDim.x + threadIdx.x;
    if (v >= n) return;
    float dv = rsqrtf(g_deg[v] + 1.0f);
    float acc[8];
    const float* xr = g_o8 + (size_t)v * 8;
#pragma unroll
    for (int f = 0; f < 8; f++) acc[f] = xr[f] * dv;
    int cnt = g_cnt[v];
    cnt = cnt > BCAP ? BCAP : cnt;
    const unsigned long long* eb = g_ebuf + (size_t)v * BCAP;
    for (int j = 0; j < cnt; j++) {
        unsigned long long p = eb[j];
        int src = (int)(unsigned)p;
        float w = __uint_as_float((unsigned)(p >> 32)) * rsqrtf(g_deg[src] + 1.0f);
        const float* r = g_o8 + (size_t)src * 8;
#pragma unroll
        for (int f = 0; f < 8; f++) acc[f] += w * r[f];
    }
#pragma unroll
    for (int f = 0; f < 8; f++) out[(size_t)v * 8 + f] = acc[f] * dv + bias[f];
}

// ---------------- launch ----------------------------------------------------
extern "C" void kernel_launch(void* const* d_in, const int* in_sizes, int n_in,
                              void* d_out, int out_size) {
    const float* x  = (const float*)d_in[0];
    const void*  ei = d_in[1];
    const float* ew = (const float*)d_in[2];
    const float* W1 = (const float*)d_in[3];
    const float* b1 = (const float*)d_in[4];
    const float* W2 = (const float*)d_in[5];
    const float* b2 = (const float*)d_in[6];
    const float* W3 = (const float*)d_in[7];
    const float* b3 = (const float*)d_in[8];
    float* out = (float*)d_out;

    int N = in_sizes[0] / 256;
    int E = in_sizes[2];

    // ---- setup + weight prep ----
    k_init_detect<<<(N + 255) / 256, 256>>>((const int*)ei, in_sizes[1], N);
    k_prep<<<(256 * 512 + 512 * 768 + 255) / 256, 256>>>(W1, W2);
    k_pass1<<<(E + 255) / 256, 256>>>(ei, ew, E, N);

    // ---- layer 1: agg(x)@256 -> g_a(frag); relu(g_a@W1+b1) -> g_h ----
    k_agg<256, 0><<<(N * 32 + 255) / 256, 256>>>(x, N);
    k_gemm_tf32<0><<<dim3(512 / 64, (N + 127) / 128), 256>>>(b1, N, 256, 512);

    // ---- layer 2: agg(g_h)@512 -> g_a(frag); relu(g_a@W2+b2) -> g_h ----
    k_agg<512, 1><<<(N * 32 + 255) / 256, 256>>>(nullptr, N);
    k_gemm_tf32<1><<<dim3(768 / 64, (N + 127) / 128), 256>>>(b2, N, 512, 768);

    // ---- layer 3: g_h@W3 -> g_o8; agg + bias -> out ----
    k_gemm8<<<(N + 31) / 32, 256>>>(W3, N, 768);
    k_agg8<<<(N + 255) / 256, 256>>>(b3, out, N);
}

// round 14
// speedup vs baseline: 1.1647x; 1.0467x over previous
#include <cuda_runtime.h>
#include <cuda_fp16.h>
#include <cstdint>

#define NMAX 10000
#define EMAX 320000
#define BCAP 128
#define AGRPS 316   // ceil(10112/32): A fragment groups incl. padding

// ---------------- scratch (static device globals; no allocation) ------------
__device__ int       g_is64;
__device__ float     g_deg[NMAX];
__device__ int       g_cnt[NMAX];
__device__ unsigned long long g_ebuf[(size_t)NMAX * BCAP];
__device__ float  g_a [(size_t)AGRPS * 64 * 256];  // A fragment layout (fp32 tf32)
__device__ __half g_x16[(size_t)NMAX * 256];       // fp16 copy of input x
__device__ __half g_h16[(size_t)NMAX * 768];       // fp16 layer activation
__device__ float  g_wb1[256 * 512];                // W1 permuted tf32
__device__ float  g_wb2[512 * 768];                // W2 permuted tf32
__device__ float  g_o8[(size_t)NMAX * 8];

// ---------------- fused init + dtype detect ---------------------------------
__global__ void k_init_detect(const int* __restrict__ ei32, int nwords, int n) {
    int i = blockIdx.x * blockDim.x + threadIdx.x;
    if (i < n) { g_deg[i] = 0.0f; g_cnt[i] = 0; }
    if (blockIdx.x == 0) {
        __shared__ int any_nonzero;
        if (threadIdx.x == 0) any_nonzero = 0;
        __syncthreads();
        int lim = nwords < 2048 ? nwords : 2048;
        for (int w = threadIdx.x * 2 + 1; w < lim; w += 512)
            if (ei32[w] != 0) atomicOr(&any_nonzero, 1);
        __syncthreads();
        if (threadIdx.x == 0) g_is64 = any_nonzero ? 0 : 1;
    }
}

__device__ __forceinline__ int load_idx(const void* ei, long long pos, int n) {
    int v = g_is64 ? (int)((const long long*)ei)[pos]
                   : ((const int*)ei)[pos];
    v = v < 0 ? 0 : (v >= n ? n - 1 : v);
    return v;
}

// ---------------- x -> fp16 conversion ---------------------------------------
__global__ void k_cvt(const float* __restrict__ x, int total2) {
    int i = blockIdx.x * blockDim.x + threadIdx.x;
    if (i >= total2) return;
    float2 v = ((const float2*)x)[i];
    ((__half2*)g_x16)[i] = __floats2half2_rn(v.x, v.y);
}

// ---------------- single edge pass: degree + bucket scatter ------------------
__global__ void k_pass1(const void* __restrict__ ei,
                        const float* __restrict__ ew, int E, int n) {
    int e = blockIdx.x * blockDim.x + threadIdx.x;
    if (e >= E) return;
    int r = load_idx(ei, e, n);
    int c = load_idx(ei, (long long)E + e, n);
    float w = ew[e];
    atomicAdd(&g_deg[c], w);
    int p = atomicAdd(&g_cnt[c], 1);
    if (p < BCAP) {
        unsigned long long packed =
            ((unsigned long long)__float_as_uint(w) << 32) | (unsigned)r;
        g_ebuf[(size_t)c * BCAP + p] = packed;
    }
}

// ---------------- helpers ----------------------------------------------------
__device__ __forceinline__ uint32_t f2tf32(float f) {
    uint32_t r;
    asm("cvt.rna.tf32.f32 %0, %1;" : "=r"(r) : "f"(f));
    return r;
}
__device__ __forceinline__ float tf32r(float f) {
    return __uint_as_float(f2tf32(f));
}
__device__ __forceinline__ void cp_async16(uint32_t smem_addr, const void* gptr) {
    asm volatile("cp.async.cg.shared.global [%0], [%1], 16;"
                 :: "r"(smem_addr), "l"(gptr));
}
__device__ __forceinline__ void cp_commit() {
    asm volatile("cp.async.commit_group;");
}
__device__ __forceinline__ void cp_wait1() {
    asm volatile("cp.async.wait_group 1;");
}

// ---------------- weight prep: permute+round W1, W2 --------------------------
__global__ void k_prep(const float* __restrict__ W1, const float* __restrict__ W2) {
    int idx = blockIdx.x * 256 + threadIdx.x;
    if (idx < 256 * 512) {
        int k = idx >> 9, n = idx & 511;           // K=256, N=512, K8=32
        float v = tf32r(W1[idx]);
        int grp = n >> 5, j = (n >> 3) & 3;
        int ln = 4 * (n & 7) + (k & 3);
        int slot = (k >> 2) & 1;
        g_wb1[((grp * 32 + (k >> 3)) * 4 + j) * 64 + ln * 2 + slot] = v;
    } else {
        int i2 = idx - 256 * 512;
        if (i2 >= 512 * 768) return;
        int k = i2 / 768, n = i2 - k * 768;        // K=512, N=768, K8=64
        float v = tf32r(W2[i2]);
        int grp = n >> 5, j = (n >> 3) & 3;
        int ln = 4 * (n & 7) + (k & 3);
        int slot = (k >> 2) & 1;
        g_wb2[((grp * 64 + (k >> 3)) * 4 + j) * 64 + ln * 2 + slot] = v;
    }
}

// ---------------- TF32 TC GEMM, fragment-layout operands --------------------
// A: g_a fragment layout (LDG.128). B: g_wb via WSEL. C -> g_h16 (fp16).
template <int WSEL>
__global__ void __launch_bounds__(256)
k_gemm_tf32(const float* __restrict__ bias, int M, int K, int N) {
    __shared__ float Bs[3][1024];
    const float* Bp = (WSEL == 0) ? (const float*)g_wb1 : (const float*)g_wb2;
    int tid = threadIdx.x;
    int lane = tid & 31, wid = tid >> 5;
    int wm = wid >> 1, wn = wid & 1;
    int bm = blockIdx.y * 128;
    int K8 = K >> 3;
    int agrp = blockIdx.y * 4 + wm;

    const float4* Ap = (const float4*)g_a;
    long a_base = ((long)agrp * K8 * 2) * 32 + lane;

    int t_grp = tid >> 7;
    int t_off = (tid & 127) * 4;
    const float* b_src = Bp + ((size_t)(blockIdx.x * 2 + t_grp) * K8) * 256 + t_off;
    uint32_t bs0 = (uint32_t)__cvta_generic_to_shared(&Bs[0][0]);
    uint32_t bdst = bs0 + (t_grp * 512 + t_off) * 4;

    float acc[2][4][4];
#pragma unroll
    for (int i = 0; i < 2; i++)
#pragma unroll
        for (int j = 0; j < 4; j++)
#pragma unroll
            for (int r = 0; r < 4; r++) acc[i][j][r] = 0.0f;

    int nIters = K >> 4;
    cp_async16(bdst, b_src);
    cp_commit();
    if (nIters > 1) cp_async16(bdst + 4096, b_src + 512);
    cp_commit();

    float4 af[2][2];
#pragma unroll
    for (int ks = 0; ks < 2; ks++)
#pragma unroll
        for (int i = 0; i < 2; i++)
            af[ks][i] = Ap[a_base + ((long)ks * 2 + i) * 32];

    int st = 0, ld = 2;
    for (int it = 0; it < nIters; it++) {
        cp_wait1();
        __syncthreads();
        if (it + 2 < nIters)
            cp_async16(bs0 + ld * 4096 + (t_grp * 512 + t_off) * 4,
                       b_src + (size_t)(it + 2) * 512);
        cp_commit();

        float4 ac[2][2];
#pragma unroll
        for (int ks = 0; ks < 2; ks++)
#pragma unroll
            for (int i = 0; i < 2; i++) ac[ks][i] = af[ks][i];
        if (it + 1 < nIters) {
            long nb = a_base + (long)(it + 1) * 4 * 32;
#pragma unroll
            for (int ks = 0; ks < 2; ks++)
#pragma unroll
                for (int i = 0; i < 2; i++)
                    af[ks][i] = Ap[nb + ((long)ks * 2 + i) * 32];
        }

#pragma unroll
        for (int ks = 0; ks < 2; ks++) {
            uint32_t a[2][4];
#pragma unroll
            for (int i = 0; i < 2; i++) {
                a[i][0] = __float_as_uint(ac[ks][i].x);
                a[i][1] = __float_as_uint(ac[ks][i].y);
                a[i][2] = __float_as_uint(ac[ks][i].z);
                a[i][3] = __float_as_uint(ac[ks][i].w);
            }
            float2 b[4];
#pragma unroll
            for (int j = 0; j < 4; j++)
                b[j] = *(const float2*)&Bs[st][((wn * 2 + ks) * 4 + j) * 64 + lane * 2];
#pragma unroll
            for (int i = 0; i < 2; i++)
#pragma unroll
                for (int j = 0; j < 4; j++) {
                    asm volatile(
                        "mma.sync.aligned.m16n8k8.row.col.f32.tf32.tf32.f32 "
                        "{%0,%1,%2,%3}, {%4,%5,%6,%7}, {%8,%9}, {%0,%1,%2,%3};\n"
                        : "+f"(acc[i][j][0]), "+f"(acc[i][j][1]),
                          "+f"(acc[i][j][2]), "+f"(acc[i][j][3])
                        : "r"(a[i][0]), "r"(a[i][1]), "r"(a[i][2]), "r"(a[i][3]),
                          "r"(__float_as_uint(b[j].x)), "r"(__float_as_uint(b[j].y)));
                }
        }
        st = (st == 2) ? 0 : st + 1;
        ld = (ld == 2) ? 0 : ld + 1;
    }

    // epilogue: bias + relu -> g_h16 (fp16, half2 stores)
    int bn = blockIdx.x * 64;
#pragma unroll
    for (int i = 0; i < 2; i++) {
#pragma unroll
        for (int j = 0; j < 4; j++) {
            int row = bm + wm * 32 + i * 16 + (lane >> 2);
            int col = bn + wn * 32 + j * 8 + (lane & 3) * 2;
            float b0 = __ldg(bias + col), b1 = __ldg(bias + col + 1);
            if (row < M) {
                *(__half2*)(g_h16 + (size_t)row * N + col) =
                    __floats2half2_rn(fmaxf(acc[i][j][0] + b0, 0.f),
                                      fmaxf(acc[i][j][1] + b1, 0.f));
            }
            if (row + 8 < M) {
                *(__half2*)(g_h16 + (size_t)(row + 8) * N + col) =
                    __floats2half2_rn(fmaxf(acc[i][j][2] + b0, 0.f),
                                      fmaxf(acc[i][j][3] + b1, 0.f));
            }
        }
    }
}

// ---------------- skinny GEMM N=8: W3 in SMEM, warp handles 4 rows ----------
__global__ void __launch_bounds__(256)
k_gemm8(const float* __restrict__ W, int M, int K) {
    __shared__ float Ws[768 * 8];
    int tid = threadIdx.x;
    for (int i = tid; i < K * 2; i += 256)
        ((float4*)Ws)[i] = ((const float4*)W)[i];
    __syncthreads();

    int wid = tid >> 5, lane = tid & 31;
    int base = (blockIdx.x * 8 + wid) * 4;
    if (base >= M) return;
    int nr = (M - base < 4) ? (M - base) : 4;

    float acc[4][8];
#pragma unroll
    for (int r = 0; r < 4; r++)
#pragma unroll
        for (int f = 0; f < 8; f++) acc[r][f] = 0.0f;

    const __half* a0 = g_h16 + (size_t)base * K;
    for (int k = lane; k < K; k += 32) {
        float4 w0 = *(const float4*)(Ws + k * 8);
        float4 w1 = *(const float4*)(Ws + k * 8 + 4);
        float av[4];
#pragma unroll
        for (int r = 0; r < 4; r++)
            av[r] = (r < nr) ? __half2float(a0[(size_t)r * K + k]) : 0.0f;
#pragma unroll
        for (int r = 0; r < 4; r++) {
            acc[r][0] += av[r] * w0.x; acc[r][1] += av[r] * w0.y;
            acc[r][2] += av[r] * w0.z; acc[r][3] += av[r] * w0.w;
            acc[r][4] += av[r] * w1.x; acc[r][5] += av[r] * w1.y;
            acc[r][6] += av[r] * w1.z; acc[r][7] += av[r] * w1.w;
        }
    }
#pragma unroll
    for (int r = 0; r < 4; r++)
#pragma unroll
        for (int f = 0; f < 8; f++)
#pragma unroll
            for (int o = 16; o > 0; o >>= 1)
                acc[r][f] += __shfl_down_sync(0xffffffffu, acc[r][f], o);
    if (lane == 0) {
#pragma unroll
        for (int r = 0; r < 4; r++)
            if (r < nr)
#pragma unroll
                for (int f = 0; f < 8; f++)
                    g_o8[(size_t)(base + r) * 8 + f] = acc[r][f];
    }
}

// ---------------- aggregation: fp16 gathers -> g_a FRAGMENT layout ----------
// Each lane loads uint2 (4 fp16) covering cols 4*lane+128*i — same grouping
// as the old float4 path, so the fragment scatter is unchanged.
template <int F, int ASRC>
__global__ void __launch_bounds__(256)
k_agg(int n) {
    int gw = (blockIdx.x * blockDim.x + threadIdx.x) >> 5;
    int lane = threadIdx.x & 31;
    if (gw >= n) return;
    const __half* X = (ASRC == 0) ? g_x16 : g_h16;
    constexpr int NV = F / 128;
    constexpr int UN = (F == 256) ? 4 : 2;
    constexpr int K8 = F / 8;
    float dv = rsqrtf(g_deg[gw] + 1.0f);
    float4 acc[NV];
    const uint2* xr = (const uint2*)(X + (size_t)gw * F);
#pragma unroll
    for (int i = 0; i < NV; i++) {
        uint2 u = xr[lane + 32 * i];
        float2 lo = __half22float2(*reinterpret_cast<const __half2*>(&u.x));
        float2 hi = __half22float2(*reinterpret_cast<const __half2*>(&u.y));
        acc[i] = make_float4(lo.x * dv, lo.y * dv, hi.x * dv, hi.y * dv);
    }
    int cnt = g_cnt[gw];
    cnt = cnt > BCAP ? BCAP : cnt;
    const unsigned long long* eb = g_ebuf + (size_t)gw * BCAP;
    int j = 0;
    for (; j + UN <= cnt; j += UN) {
        const uint2* rp[UN];
        float wv[UN];
#pragma unroll
        for (int u = 0; u < UN; u++) {
            unsigned long long p = eb[j + u];
            int src = (int)(unsigned)p;
            float w = __uint_as_float((unsigned)(p >> 32));
            wv[u] = w * rsqrtf(g_deg[src] + 1.0f);
            rp[u] = (const uint2*)(X + (size_t)src * F);
        }
#pragma unroll
        for (int i = 0; i < NV; i++) {
            uint2 us[UN];
#pragma unroll
            for (int u = 0; u < UN; u++) us[u] = rp[u][lane + 32 * i];
#pragma unroll
            for (int u = 0; u < UN; u++) {
                float2 lo = __half22float2(*reinterpret_cast<const __half2*>(&us[u].x));
                float2 hi = __half22float2(*reinterpret_cast<const __half2*>(&us[u].y));
                acc[i].x += wv[u] * lo.x;
                acc[i].y += wv[u] * lo.y;
                acc[i].z += wv[u] * hi.x;
                acc[i].w += wv[u] * hi.y;
            }
        }
    }
    for (; j < cnt; j++) {
        unsigned long long p = eb[j];
        int src = (int)(unsigned)p;
        float w0 = __uint_as_float((unsigned)(p >> 32)) * rsqrtf(g_deg[src] + 1.0f);
        const uint2* r0 = (const uint2*)(X + (size_t)src * F);
#pragma unroll
        for (int i = 0; i < NV; i++) {
            uint2 u = r0[lane + 32 * i];
            float2 lo = __half22float2(*reinterpret_cast<const __half2*>(&u.x));
            float2 hi = __half22float2(*reinterpret_cast<const __half2*>(&u.y));
            acc[i].x += w0 * lo.x;
            acc[i].y += w0 * lo.y;
            acc[i].z += w0 * hi.x;
            acc[i].w += w0 * hi.y;
        }
    }
    // scatter into A fragment layout, tf32-rounded (unchanged)
    int grp = gw >> 5, rr = gw & 31;
    int i16 = rr >> 4, row8 = rr & 15;
    int sb = (row8 >> 3) + 2 * (lane & 1);
    int lp4 = (row8 & 7) * 16;
#pragma unroll
    for (int q = 0; q < NV; q++) {
        int k8 = (lane >> 1) + 16 * q;
        long base = ((long)(grp * K8 + k8) * 2 + i16) * 128 + lp4 + sb;
        g_a[base + 0]  = tf32r(acc[q].x * dv);
        g_a[base + 4]  = tf32r(acc[q].y * dv);
        g_a[base + 8]  = tf32r(acc[q].z * dv);
        g_a[base + 12] = tf32r(acc[q].w * dv);
    }
}

// ---------------- aggregation F=8 (+bias), writes d_out ---------------------
__global__ void k_agg8(const float* __restrict__ bias, float* __restrict__ out,
                       int n) {
    int v = blockIdx.x * blockDim.x + threadIdx.x;
    if (v >= n) return;
    float dv = rsqrtf(g_deg[v] + 1.0f);
    float acc[8];
    const float* xr = g_o8 + (size_t)v * 8;
#pragma unroll
    for (int f = 0; f < 8; f++) acc[f] = xr[f] * dv;
    int cnt = g_cnt[v];
    cnt = cnt > BCAP ? BCAP : cnt;
    const unsigned long long* eb = g_ebuf + (size_t)v * BCAP;
    for (int j = 0; j < cnt; j++) {
        unsigned long long p = eb[j];
        int src = (int)(unsigned)p;
        float w = __uint_as_float((unsigned)(p >> 32)) * rsqrtf(g_deg[src] + 1.0f);
        const float* r = g_o8 + (size_t)src * 8;
#pragma unroll
        for (int f = 0; f < 8; f++) acc[f] += w * r[f];
    }
#pragma unroll
    for (int f = 0; f < 8; f++) out[(size_t)v * 8 + f] = acc[f] * dv + bias[f];
}

// ---------------- launch ----------------------------------------------------
extern "C" void kernel_launch(void* const* d_in, const int* in_sizes, int n_in,
                              void* d_out, int out_size) {
    const float* x  = (const float*)d_in[0];
    const void*  ei = d_in[1];
    const float* ew = (const float*)d_in[2];
    const float* W1 = (const float*)d_in[3];
    const float* b1 = (const float*)d_in[4];
    const float* W2 = (const float*)d_in[5];
    const float* b2 = (const float*)d_in[6];
    const float* W3 = (const float*)d_in[7];
    const float* b3 = (const float*)d_in[8];
    float* out = (float*)d_out;

    int N = in_sizes[0] / 256;
    int E = in_sizes[2];

    // ---- setup + weight prep + x conversion ----
    k_init_detect<<<(N + 255) / 256, 256>>>((const int*)ei, in_sizes[1], N);
    k_prep<<<(256 * 512 + 512 * 768 + 255) / 256, 256>>>(W1, W2);
    k_cvt<<<(N * 128 + 255) / 256, 256>>>(x, N * 128);
    k_pass1<<<(E + 255) / 256, 256>>>(ei, ew, E, N);

    // ---- layer 1: agg(x16)@256 -> g_a(frag); relu(g_a@W1+b1) -> g_h16 ----
    k_agg<256, 0><<<(N * 32 + 255) / 256, 256>>>(N);
    k_gemm_tf32<0><<<dim3(512 / 64, (N + 127) / 128), 256>>>(b1, N, 256, 512);

    // ---- layer 2: agg(g_h16)@512 -> g_a(frag); relu(g_a@W2+b2) -> g_h16 ----
    k_agg<512, 1><<<(N * 32 + 255) / 256, 256>>>(N);
    k_gemm_tf32<1><<<dim3(768 / 64, (N + 127) / 128), 256>>>(b2, N, 512, 768);

    // ---- layer 3: g_h16@W3 -> g_o8; agg + bias -> out ----
    k_gemm8<<<(N + 31) / 32, 256>>>(W3, N, 768);
    k_agg8<<<(N + 255) / 256, 256>>>(b3, out, N);
}

// round 15
// speedup vs baseline: 1.1864x; 1.0186x over previous
#include <cuda_runtime.h>
#include <cuda_fp16.h>
#include <cstdint>

#define NMAX 10000
#define EMAX 320000
#define BCAP 128
#define AGRPS 316   // ceil(10112/32): A fragment groups incl. padding

// ---------------- scratch (static device globals; no allocation) ------------
__device__ int       g_is64;
__device__ float     g_deg[NMAX];
__device__ int       g_cnt[NMAX];
__device__ unsigned long long g_ebuf[(size_t)NMAX * BCAP];
__device__ float  g_a [(size_t)AGRPS * 64 * 256];  // A fragment layout (fp32 tf32)
__device__ __half g_x16[(size_t)NMAX * 256];       // fp16 copy of input x
__device__ __half g_h16[(size_t)NMAX * 768];       // fp16 layer activation
__device__ float  g_wb1[256 * 512];                // W1 permuted tf32
__device__ float  g_wb2[512 * 768];                // W2 permuted tf32
__device__ float  g_o8[(size_t)NMAX * 8];

// ---------------- fused init + dtype detect ---------------------------------
__global__ void k_init_detect(const int* __restrict__ ei32, int nwords, int n) {
    int i = blockIdx.x * blockDim.x + threadIdx.x;
    if (i < n) { g_deg[i] = 0.0f; g_cnt[i] = 0; }
    if (blockIdx.x == 0) {
        __shared__ int any_nonzero;
        if (threadIdx.x == 0) any_nonzero = 0;
        __syncthreads();
        int lim = nwords < 2048 ? nwords : 2048;
        for (int w = threadIdx.x * 2 + 1; w < lim; w += 512)
            if (ei32[w] != 0) atomicOr(&any_nonzero, 1);
        __syncthreads();
        if (threadIdx.x == 0) g_is64 = any_nonzero ? 0 : 1;
    }
}

__device__ __forceinline__ int load_idx(const void* ei, long long pos, int n) {
    int v = g_is64 ? (int)((const long long*)ei)[pos]
                   : ((const int*)ei)[pos];
    v = v < 0 ? 0 : (v >= n ? n - 1 : v);
    return v;
}

// ---------------- x -> fp16 conversion ---------------------------------------
__global__ void k_cvt(const float* __restrict__ x, int total2) {
    int i = blockIdx.x * blockDim.x + threadIdx.x;
    if (i >= total2) return;
    float2 v = ((const float2*)x)[i];
    ((__half2*)g_x16)[i] = __floats2half2_rn(v.x, v.y);
}

// ---------------- single edge pass: degree + bucket scatter ------------------
__global__ void k_pass1(const void* __restrict__ ei,
                        const float* __restrict__ ew, int E, int n) {
    int e = blockIdx.x * blockDim.x + threadIdx.x;
    if (e >= E) return;
    int r = load_idx(ei, e, n);
    int c = load_idx(ei, (long long)E + e, n);
    float w = ew[e];
    atomicAdd(&g_deg[c], w);
    int p = atomicAdd(&g_cnt[c], 1);
    if (p < BCAP) {
        unsigned long long packed =
            ((unsigned long long)__float_as_uint(w) << 32) | (unsigned)r;
        g_ebuf[(size_t)c * BCAP + p] = packed;
    }
}

// ---------------- normalize bucket weights: w -> w * rsqrt(deg[src]+1) ------
__global__ void k_norm(int n) {
    int gw = (blockIdx.x * blockDim.x + threadIdx.x) >> 5;
    int lane = threadIdx.x & 31;
    if (gw >= n) return;
    int cnt = g_cnt[gw];
    cnt = cnt > BCAP ? BCAP : cnt;
    unsigned long long* eb = g_ebuf + (size_t)gw * BCAP;
    for (int j = lane; j < cnt; j += 32) {
        unsigned long long p = eb[j];
        int src = (int)(unsigned)p;
        float w = __uint_as_float((unsigned)(p >> 32));
        w *= rsqrtf(g_deg[src] + 1.0f);
        eb[j] = ((unsigned long long)__float_as_uint(w) << 32) | (unsigned)src;
    }
}

// ---------------- helpers ----------------------------------------------------
__device__ __forceinline__ uint32_t f2tf32(float f) {
    uint32_t r;
    asm("cvt.rna.tf32.f32 %0, %1;" : "=r"(r) : "f"(f));
    return r;
}
__device__ __forceinline__ float tf32r(float f) {
    return __uint_as_float(f2tf32(f));
}
__device__ __forceinline__ void cp_async16(uint32_t smem_addr, const void* gptr) {
    asm volatile("cp.async.cg.shared.global [%0], [%1], 16;"
                 :: "r"(smem_addr), "l"(gptr));
}
__device__ __forceinline__ void cp_commit() {
    asm volatile("cp.async.commit_group;");
}
__device__ __forceinline__ void cp_wait1() {
    asm volatile("cp.async.wait_group 1;");
}

// ---------------- weight prep: permute+round W1, W2 --------------------------
__global__ void k_prep(const float* __restrict__ W1, const float* __restrict__ W2) {
    int idx = blockIdx.x * 256 + threadIdx.x;
    if (idx < 256 * 512) {
        int k = idx >> 9, n = idx & 511;           // K=256, N=512, K8=32
        float v = tf32r(W1[idx]);
        int grp = n >> 5, j = (n >> 3) & 3;
        int ln = 4 * (n & 7) + (k & 3);
        int slot = (k >> 2) & 1;
        g_wb1[((grp * 32 + (k >> 3)) * 4 + j) * 64 + ln * 2 + slot] = v;
    } else {
        int i2 = idx - 256 * 512;
        if (i2 >= 512 * 768) return;
        int k = i2 / 768, n = i2 - k * 768;        // K=512, N=768, K8=64
        float v = tf32r(W2[i2]);
        int grp = n >> 5, j = (n >> 3) & 3;
        int ln = 4 * (n & 7) + (k & 3);
        int slot = (k >> 2) & 1;
        g_wb2[((grp * 64 + (k >> 3)) * 4 + j) * 64 + ln * 2 + slot] = v;
    }
}

// ---------------- TF32 TC GEMM, fragment-layout operands --------------------
// A: g_a fragment layout (LDG.128). B: g_wb via WSEL. C -> g_h16 (fp16).
template <int WSEL>
__global__ void __launch_bounds__(256)
k_gemm_tf32(const float* __restrict__ bias, int M, int K, int N) {
    __shared__ float Bs[3][1024];
    const float* Bp = (WSEL == 0) ? (const float*)g_wb1 : (const float*)g_wb2;
    int tid = threadIdx.x;
    int lane = tid & 31, wid = tid >> 5;
    int wm = wid >> 1, wn = wid & 1;
    int bm = blockIdx.y * 128;
    int K8 = K >> 3;
    int agrp = blockIdx.y * 4 + wm;

    const float4* Ap = (const float4*)g_a;
    long a_base = ((long)agrp * K8 * 2) * 32 + lane;

    int t_grp = tid >> 7;
    int t_off = (tid & 127) * 4;
    const float* b_src = Bp + ((size_t)(blockIdx.x * 2 + t_grp) * K8) * 256 + t_off;
    uint32_t bs0 = (uint32_t)__cvta_generic_to_shared(&Bs[0][0]);
    uint32_t bdst = bs0 + (t_grp * 512 + t_off) * 4;

    float acc[2][4][4];
#pragma unroll
    for (int i = 0; i < 2; i++)
#pragma unroll
        for (int j = 0; j < 4; j++)
#pragma unroll
            for (int r = 0; r < 4; r++) acc[i][j][r] = 0.0f;

    int nIters = K >> 4;
    cp_async16(bdst, b_src);
    cp_commit();
    if (nIters > 1) cp_async16(bdst + 4096, b_src + 512);
    cp_commit();

    float4 af[2][2];
#pragma unroll
    for (int ks = 0; ks < 2; ks++)
#pragma unroll
        for (int i = 0; i < 2; i++)
            af[ks][i] = Ap[a_base + ((long)ks * 2 + i) * 32];

    int st = 0, ld = 2;
    for (int it = 0; it < nIters; it++) {
        cp_wait1();
        __syncthreads();
        if (it + 2 < nIters)
            cp_async16(bs0 + ld * 4096 + (t_grp * 512 + t_off) * 4,
                       b_src + (size_t)(it + 2) * 512);
        cp_commit();

        float4 ac[2][2];
#pragma unroll
        for (int ks = 0; ks < 2; ks++)
#pragma unroll
            for (int i = 0; i < 2; i++) ac[ks][i] = af[ks][i];
        if (it + 1 < nIters) {
            long nb = a_base + (long)(it + 1) * 4 * 32;
#pragma unroll
            for (int ks = 0; ks < 2; ks++)
#pragma unroll
                for (int i = 0; i < 2; i++)
                    af[ks][i] = Ap[nb + ((long)ks * 2 + i) * 32];
        }

#pragma unroll
        for (int ks = 0; ks < 2; ks++) {
            uint32_t a[2][4];
#pragma unroll
            for (int i = 0; i < 2; i++) {
                a[i][0] = __float_as_uint(ac[ks][i].x);
                a[i][1] = __float_as_uint(ac[ks][i].y);
                a[i][2] = __float_as_uint(ac[ks][i].z);
                a[i][3] = __float_as_uint(ac[ks][i].w);
            }
            float2 b[4];
#pragma unroll
            for (int j = 0; j < 4; j++)
                b[j] = *(const float2*)&Bs[st][((wn * 2 + ks) * 4 + j) * 64 + lane * 2];
#pragma unroll
            for (int i = 0; i < 2; i++)
#pragma unroll
                for (int j = 0; j < 4; j++) {
                    asm volatile(
                        "mma.sync.aligned.m16n8k8.row.col.f32.tf32.tf32.f32 "
                        "{%0,%1,%2,%3}, {%4,%5,%6,%7}, {%8,%9}, {%0,%1,%2,%3};\n"
                        : "+f"(acc[i][j][0]), "+f"(acc[i][j][1]),
                          "+f"(acc[i][j][2]), "+f"(acc[i][j][3])
                        : "r"(a[i][0]), "r"(a[i][1]), "r"(a[i][2]), "r"(a[i][3]),
                          "r"(__float_as_uint(b[j].x)), "r"(__float_as_uint(b[j].y)));
                }
        }
        st = (st == 2) ? 0 : st + 1;
        ld = (ld == 2) ? 0 : ld + 1;
    }

    // epilogue: bias + relu -> g_h16 (fp16, half2 stores)
    int bn = blockIdx.x * 64;
#pragma unroll
    for (int i = 0; i < 2; i++) {
#pragma unroll
        for (int j = 0; j < 4; j++) {
            int row = bm + wm * 32 + i * 16 + (lane >> 2);
            int col = bn + wn * 32 + j * 8 + (lane & 3) * 2;
            float b0 = __ldg(bias + col), b1 = __ldg(bias + col + 1);
            if (row < M) {
                *(__half2*)(g_h16 + (size_t)row * N + col) =
                    __floats2half2_rn(fmaxf(acc[i][j][0] + b0, 0.f),
                                      fmaxf(acc[i][j][1] + b1, 0.f));
            }
            if (row + 8 < M) {
                *(__half2*)(g_h16 + (size_t)(row + 8) * N + col) =
                    __floats2half2_rn(fmaxf(acc[i][j][2] + b0, 0.f),
                                      fmaxf(acc[i][j][3] + b1, 0.f));
            }
        }
    }
}

// ---------------- skinny GEMM N=8: W3 in SMEM, warp handles 4 rows ----------
__global__ void __launch_bounds__(256)
k_gemm8(const float* __restrict__ W, int M, int K) {
    __shared__ float Ws[768 * 8];
    int tid = threadIdx.x;
    for (int i = tid; i < K * 2; i += 256)
        ((float4*)Ws)[i] = ((const float4*)W)[i];
    __syncthreads();

    int wid = tid >> 5, lane = tid & 31;
    int base = (blockIdx.x * 8 + wid) * 4;
    if (base >= M) return;
    int nr = (M - base < 4) ? (M - base) : 4;

    float acc[4][8];
#pragma unroll
    for (int r = 0; r < 4; r++)
#pragma unroll
        for (int f = 0; f < 8; f++) acc[r][f] = 0.0f;

    const __half* a0 = g_h16 + (size_t)base * K;
    for (int k = lane; k < K; k += 32) {
        float4 w0 = *(const float4*)(Ws + k * 8);
        float4 w1 = *(const float4*)(Ws + k * 8 + 4);
        float av[4];
#pragma unroll
        for (int r = 0; r < 4; r++)
            av[r] = (r < nr) ? __half2float(a0[(size_t)r * K + k]) : 0.0f;
#pragma unroll
        for (int r = 0; r < 4; r++) {
            acc[r][0] += av[r] * w0.x; acc[r][1] += av[r] * w0.y;
            acc[r][2] += av[r] * w0.z; acc[r][3] += av[r] * w0.w;
            acc[r][4] += av[r] * w1.x; acc[r][5] += av[r] * w1.y;
            acc[r][6] += av[r] * w1.z; acc[r][7] += av[r] * w1.w;
        }
    }
#pragma unroll
    for (int r = 0; r < 4; r++)
#pragma unroll
        for (int f = 0; f < 8; f++)
#pragma unroll
            for (int o = 16; o > 0; o >>= 1)
                acc[r][f] += __shfl_down_sync(0xffffffffu, acc[r][f], o);
    if (lane == 0) {
#pragma unroll
        for (int r = 0; r < 4; r++)
            if (r < nr)
#pragma unroll
                for (int f = 0; f < 8; f++)
                    g_o8[(size_t)(base + r) * 8 + f] = acc[r][f];
    }
}

// ---------------- aggregation: fp16 gathers -> g_a FRAGMENT layout ----------
// Bucket weights are pre-normalized (w already includes rsqrt(deg[src]+1)).
template <int F, int ASRC>
__global__ void __launch_bounds__(256)
k_agg(int n) {
    int gw = (blockIdx.x * blockDim.x + threadIdx.x) >> 5;
    int lane = threadIdx.x & 31;
    if (gw >= n) return;
    const __half* X = (ASRC == 0) ? g_x16 : g_h16;
    constexpr int NV = F / 128;
    constexpr int UN = (F == 256) ? 8 : 4;
    constexpr int K8 = F / 8;
    float dv = rsqrtf(g_deg[gw] + 1.0f);
    float4 acc[NV];
    const uint2* xr = (const uint2*)(X + (size_t)gw * F);
#pragma unroll
    for (int i = 0; i < NV; i++) {
        uint2 u = xr[lane + 32 * i];
        float2 lo = __half22float2(*reinterpret_cast<const __half2*>(&u.x));
        float2 hi = __half22float2(*reinterpret_cast<const __half2*>(&u.y));
        acc[i] = make_float4(lo.x * dv, lo.y * dv, hi.x * dv, hi.y * dv);
    }
    int cnt = g_cnt[gw];
    cnt = cnt > BCAP ? BCAP : cnt;
    const unsigned long long* eb = g_ebuf + (size_t)gw * BCAP;
    int j = 0;
    for (; j + UN <= cnt; j += UN) {
        const uint2* rp[UN];
        float wv[UN];
#pragma unroll
        for (int u = 0; u < UN; u++) {
            unsigned long long p = eb[j + u];
            int src = (int)(unsigned)p;
            wv[u] = __uint_as_float((unsigned)(p >> 32));
            rp[u] = (const uint2*)(X + (size_t)src * F);
        }
#pragma unroll
        for (int i = 0; i < NV; i++) {
            uint2 us[UN];
#pragma unroll
            for (int u = 0; u < UN; u++) us[u] = rp[u][lane + 32 * i];
#pragma unroll
            for (int u = 0; u < UN; u++) {
                float2 lo = __half22float2(*reinterpret_cast<const __half2*>(&us[u].x));
                float2 hi = __half22float2(*reinterpret_cast<const __half2*>(&us[u].y));
                acc[i].x += wv[u] * lo.x;
                acc[i].y += wv[u] * lo.y;
                acc[i].z += wv[u] * hi.x;
                acc[i].w += wv[u] * hi.y;
            }
        }
    }
    for (; j < cnt; j++) {
        unsigned long long p = eb[j];
        int src = (int)(unsigned)p;
        float w0 = __uint_as_float((unsigned)(p >> 32));
        const uint2* r0 = (const uint2*)(X + (size_t)src * F);
#pragma unroll
        for (int i = 0; i < NV; i++) {
            uint2 u = r0[lane + 32 * i];
            float2 lo = __half22float2(*reinterpret_cast<const __half2*>(&u.x));
            float2 hi = __half22float2(*reinterpret_cast<const __half2*>(&u.y));
            acc[i].x += w0 * lo.x;
            acc[i].y += w0 * lo.y;
            acc[i].z += w0 * hi.x;
            acc[i].w += w0 * hi.y;
        }
    }
    // scatter into A fragment layout, tf32-rounded (unchanged)
    int grp = gw >> 5, rr = gw & 31;
    int i16 = rr >> 4, row8 = rr & 15;
    int sb = (row8 >> 3) + 2 * (lane & 1);
    int lp4 = (row8 & 7) * 16;
#pragma unroll
    for (int q = 0; q < NV; q++) {
        int k8 = (lane >> 1) + 16 * q;
        long base = ((long)(grp * K8 + k8) * 2 + i16) * 128 + lp4 + sb;
        g_a[base + 0]  = tf32r(acc[q].x * dv);
        g_a[base + 4]  = tf32r(acc[q].y * dv);
        g_a[base + 8]  = tf32r(acc[q].z * dv);
        g_a[base + 12] = tf32r(acc[q].w * dv);
    }
}

// ---------------- aggregation F=8 (+bias), writes d_out ---------------------
__global__ void k_agg8(const float* __restrict__ bias, float* __restrict__ out,
                       int n) {
    int v = blockIdx.x * blockDim.x + threadIdx.x;
    if (v >= n) return;
    float dv = rsqrtf(g_deg[v] + 1.0f);
    float acc[8];
    const float* xr = g_o8 + (size_t)v * 8;
#pragma unroll
    for (int f = 0; f < 8; f++) acc[f] = xr[f] * dv;
    int cnt = g_cnt[v];
    cnt = cnt > BCAP ? BCAP : cnt;
    const unsigned long long* eb = g_ebuf + (size_t)v * BCAP;
    for (int j = 0; j < cnt; j++) {
        unsigned long long p = eb[j];
        int src = (int)(unsigned)p;
        float w = __uint_as_float((unsigned)(p >> 32));
        const float* r = g_o8 + (size_t)src * 8;
#pragma unroll
        for (int f = 0; f < 8; f++) acc[f] += w * r[f];
    }
#pragma unroll
    for (int f = 0; f < 8; f++) out[(size_t)v * 8 + f] = acc[f] * dv + bias[f];
}

// ---------------- launch ----------------------------------------------------
extern "C" void kernel_launch(void* const* d_in, const int* in_sizes, int n_in,
                              void* d_out, int out_size) {
    const float* x  = (const float*)d_in[0];
    const void*  ei = d_in[1];
    const float* ew = (const float*)d_in[2];
    const float* W1 = (const float*)d_in[3];
    const float* b1 = (const float*)d_in[4];
    const float* W2 = (const float*)d_in[5];
    const float* b2 = (const float*)d_in[6];
    const float* W3 = (const float*)d_in[7];
    const float* b3 = (const float*)d_in[8];
    float* out = (float*)d_out;

    int N = in_sizes[0] / 256;
    int E = in_sizes[2];

    // ---- setup + weight prep + x conversion ----
    k_init_detect<<<(N + 255) / 256, 256>>>((const int*)ei, in_sizes[1], N);
    k_prep<<<(256 * 512 + 512 * 768 + 255) / 256, 256>>>(W1, W2);
    k_cvt<<<(N * 128 + 255) / 256, 256>>>(x, N * 128);
    k_pass1<<<(E + 255) / 256, 256>>>(ei, ew, E, N);
    k_norm<<<(N * 32 + 255) / 256, 256>>>(N);

    // ---- layer 1: agg(x16)@256 -> g_a(frag); relu(g_a@W1+b1) -> g_h16 ----
    k_agg<256, 0><<<(N * 32 + 255) / 256, 256>>>(N);
    k_gemm_tf32<0><<<dim3(512 / 64, (N + 127) / 128), 256>>>(b1, N, 256, 512);

    // ---- layer 2: agg(g_h16)@512 -> g_a(frag); relu(g_a@W2+b2) -> g_h16 ----
    k_agg<512, 1><<<(N * 32 + 255) / 256, 256>>>(N);
    k_gemm_tf32<1><<<dim3(768 / 64, (N + 127) / 128), 256>>>(b2, N, 512, 768);

    // ---- layer 3: g_h16@W3 -> g_o8; agg + bias -> out ----
    k_gemm8<<<(N + 31) / 32, 256>>>(W3, N, 768);
    k_agg8<<<(N + 255) / 256, 256>>>(b3, out, N);
}

// round 16
// speedup vs baseline: 1.5144x; 1.2764x over previous
#include <cuda_runtime.h>
#include <cuda_fp16.h>
#include <cstdint>

#define NMAX 10000
#define EMAX 320000
#define BCAP 128
#define AGRPS 316   // ceil(10112/32): A fragment groups incl. padding

// ---------------- scratch (static device globals; no allocation) ------------
__device__ int       g_is64;
__device__ float     g_deg[NMAX];
__device__ int       g_cnt[NMAX];
__device__ unsigned long long g_ebuf[(size_t)NMAX * BCAP];
__device__ __half2 g_a16[(size_t)AGRPS * 32 * 2 * 128]; // A fp16 frag layout (K16max=32)
__device__ __half  g_x16[(size_t)NMAX * 256];           // fp16 copy of input x
__device__ __half  g_h16[(size_t)NMAX * 768];           // fp16 layer activation
__device__ __half2 g_wb1[256 * 512 / 2];                // W1 permuted fp16
__device__ __half2 g_wb2[512 * 768 / 2];                // W2 permuted fp16
__device__ float   g_o8[(size_t)NMAX * 8];

// ---------------- fused init + dtype detect ---------------------------------
__global__ void k_init_detect(const int* __restrict__ ei32, int nwords, int n) {
    int i = blockIdx.x * blockDim.x + threadIdx.x;
    if (i < n) { g_deg[i] = 0.0f; g_cnt[i] = 0; }
    if (blockIdx.x == 0) {
        __shared__ int any_nonzero;
        if (threadIdx.x == 0) any_nonzero = 0;
        __syncthreads();
        int lim = nwords < 2048 ? nwords : 2048;
        for (int w = threadIdx.x * 2 + 1; w < lim; w += 512)
            if (ei32[w] != 0) atomicOr(&any_nonzero, 1);
        __syncthreads();
        if (threadIdx.x == 0) g_is64 = any_nonzero ? 0 : 1;
    }
}

__device__ __forceinline__ int load_idx(const void* ei, long long pos, int n) {
    int v = g_is64 ? (int)((const long long*)ei)[pos]
                   : ((const int*)ei)[pos];
    v = v < 0 ? 0 : (v >= n ? n - 1 : v);
    return v;
}

// ---------------- x -> fp16 conversion ---------------------------------------
__global__ void k_cvt(const float* __restrict__ x, int total2) {
    int i = blockIdx.x * blockDim.x + threadIdx.x;
    if (i >= total2) return;
    float2 v = ((const float2*)x)[i];
    ((__half2*)g_x16)[i] = __floats2half2_rn(v.x, v.y);
}

// ---------------- single edge pass: degree + bucket scatter ------------------
__global__ void k_pass1(const void* __restrict__ ei,
                        const float* __restrict__ ew, int E, int n) {
    int e = blockIdx.x * blockDim.x + threadIdx.x;
    if (e >= E) return;
    int r = load_idx(ei, e, n);
    int c = load_idx(ei, (long long)E + e, n);
    float w = ew[e];
    atomicAdd(&g_deg[c], w);
    int p = atomicAdd(&g_cnt[c], 1);
    if (p < BCAP) {
        unsigned long long packed =
            ((unsigned long long)__float_as_uint(w) << 32) | (unsigned)r;
        g_ebuf[(size_t)c * BCAP + p] = packed;
    }
}

// ---------------- normalize bucket weights: w -> w * rsqrt(deg[src]+1) ------
__global__ void k_norm(int n) {
    int gw = (blockIdx.x * blockDim.x + threadIdx.x) >> 5;
    int lane = threadIdx.x & 31;
    if (gw >= n) return;
    int cnt = g_cnt[gw];
    cnt = cnt > BCAP ? BCAP : cnt;
    unsigned long long* eb = g_ebuf + (size_t)gw * BCAP;
    for (int j = lane; j < cnt; j += 32) {
        unsigned long long p = eb[j];
        int src = (int)(unsigned)p;
        float w = __uint_as_float((unsigned)(p >> 32));
        w *= rsqrtf(g_deg[src] + 1.0f);
        eb[j] = ((unsigned long long)__float_as_uint(w) << 32) | (unsigned)src;
    }
}

// ---------------- helpers ----------------------------------------------------
__device__ __forceinline__ void cp_async8(uint32_t smem_addr, const void* gptr) {
    asm volatile("cp.async.ca.shared.global [%0], [%1], 8;"
                 :: "r"(smem_addr), "l"(gptr));
}
__device__ __forceinline__ void cp_commit() {
    asm volatile("cp.async.commit_group;");
}
__device__ __forceinline__ void cp_wait1() {
    asm volatile("cp.async.wait_group 1;");
}

// ---------------- weight prep: permute W -> fp16 fragment feed layout -------
// half2 idx = ((grp*K16 + k16)*4 + j)*64 + ln*2 + slot; half parity = k&1.
// ln = 4*(n&7) + ((k&15)>>1 & 3 ... t); slot = (k&15)>>3.
__global__ void k_prep(const float* __restrict__ W1, const float* __restrict__ W2) {
    int idx = blockIdx.x * 256 + threadIdx.x;
    if (idx < 256 * 512) {
        int k = idx >> 9, n = idx & 511;           // K=256 (K16=16), N=512
        __half v = __float2half_rn(W1[idx]);
        int kr = k & 15;
        int grp = n >> 5, j = (n >> 3) & 3;
        int ln = 4 * (n & 7) + ((kr >> 1) & 3);
        int slot = kr >> 3;
        long h2i = ((long)(grp * 16 + (k >> 4)) * 4 + j) * 64 + ln * 2 + slot;
        ((__half*)g_wb1)[h2i * 2 + (k & 1)] = v;
    } else {
        int i2 = idx - 256 * 512;
        if (i2 >= 512 * 768) return;
        int k = i2 / 768, n = i2 - k * 768;        // K=512 (K16=32), N=768
        __half v = __float2half_rn(W2[i2]);
        int kr = k & 15;
        int grp = n >> 5, j = (n >> 3) & 3;
        int ln = 4 * (n & 7) + ((kr >> 1) & 3);
        int slot = kr >> 3;
        long h2i = ((long)(grp * 32 + (k >> 4)) * 4 + j) * 64 + ln * 2 + slot;
        ((__half*)g_wb2)[h2i * 2 + (k & 1)] = v;
    }
}

// ---------------- FP16 TC GEMM (m16n8k16), fragment-layout operands ---------
// A: g_a16 (one LDG.128 per lane per tile). B: g_wb via cp.async (2KB/k16).
// C = relu(A@B + bias) -> g_h16. BM=128, BN=64, 256 threads, 8 warps (4x2).
template <int WSEL>
__global__ void __launch_bounds__(256)
k_gemm_fp16(const float* __restrict__ bias, int M, int K, int N) {
    __shared__ __half2 Bs[3][512];   // 3 stages x 2KB
    const __half2* Bp = WSEL ? (const __half2*)g_wb2 : (const __half2*)g_wb1;
    int tid = threadIdx.x;
    int lane = tid & 31, wid = tid >> 5;
    int wm = wid >> 1, wn = wid & 1;
    int bm = blockIdx.y * 128;
    int K16 = K >> 4;
    int agrp = blockIdx.y * 4 + wm;

    const uint4* Ap = (const uint4*)g_a16;
    long a_base = (long)agrp * K16 * 64 + lane;   // uint4 index

    int t_grp = tid >> 7;
    int t_off = (tid & 127) * 2;                  // half2 offset within grp chunk
    const __half2* b_src = Bp + ((size_t)(blockIdx.x * 2 + t_grp) * K16) * 256 + t_off;
    uint32_t bs0 = (uint32_t)__cvta_generic_to_shared(&Bs[0][0]);
    uint32_t boff = (t_grp * 256 + t_off) * 4;

    float acc[2][4][4];
#pragma unroll
    for (int i = 0; i < 2; i++)
#pragma unroll
        for (int j = 0; j < 4; j++)
#pragma unroll
            for (int r = 0; r < 4; r++) acc[i][j][r] = 0.0f;

    cp_async8(bs0 + boff, b_src);
    cp_commit();
    if (K16 > 1) cp_async8(bs0 + 2048 + boff, b_src + 256);
    cp_commit();

    uint4 af0 = Ap[a_base], af1 = Ap[a_base + 32];

    int st = 0, ld = 2;
    for (int it = 0; it < K16; it++) {
        cp_wait1();
        __syncthreads();
        if (it + 2 < K16)
            cp_async8(bs0 + ld * 2048 + boff, b_src + (size_t)(it + 2) * 256);
        cp_commit();

        uint4 aa[2] = {af0, af1};
        if (it + 1 < K16) {
            long nb = a_base + (long)(it + 1) * 64;
            af0 = Ap[nb];
            af1 = Ap[nb + 32];
        }

#pragma unroll
        for (int j = 0; j < 4; j++) {
            uint2 bb = *(const uint2*)&Bs[st][wn * 256 + j * 64 + lane * 2];
#pragma unroll
            for (int i = 0; i < 2; i++) {
                asm volatile(
                    "mma.sync.aligned.m16n8k16.row.col.f32.f16.f16.f32 "
                    "{%0,%1,%2,%3}, {%4,%5,%6,%7}, {%8,%9}, {%0,%1,%2,%3};\n"
                    : "+f"(acc[i][j][0]), "+f"(acc[i][j][1]),
                      "+f"(acc[i][j][2]), "+f"(acc[i][j][3])
                    : "r"(aa[i].x), "r"(aa[i].y), "r"(aa[i].z), "r"(aa[i].w),
                      "r"(bb.x), "r"(bb.y));
            }
        }
        st = (st == 2) ? 0 : st + 1;
        ld = (ld == 2) ? 0 : ld + 1;
    }

    // epilogue: bias + relu -> g_h16 (fp16, half2 stores)
    int bn = blockIdx.x * 64;
#pragma unroll
    for (int i = 0; i < 2; i++) {
#pragma unroll
        for (int j = 0; j < 4; j++) {
            int row = bm + wm * 32 + i * 16 + (lane >> 2);
            int col = bn + wn * 32 + j * 8 + (lane & 3) * 2;
            float b0 = __ldg(bias + col), b1 = __ldg(bias + col + 1);
            if (row < M) {
                *(__half2*)(g_h16 + (size_t)row * N + col) =
                    __floats2half2_rn(fmaxf(acc[i][j][0] + b0, 0.f),
                                      fmaxf(acc[i][j][1] + b1, 0.f));
            }
            if (row + 8 < M) {
                *(__half2*)(g_h16 + (size_t)(row + 8) * N + col) =
                    __floats2half2_rn(fmaxf(acc[i][j][2] + b0, 0.f),
                                      fmaxf(acc[i][j][3] + b1, 0.f));
            }
        }
    }
}

// ---------------- skinny GEMM N=8: W3 in SMEM, warp handles 4 rows ----------
__global__ void __launch_bounds__(256)
k_gemm8(const float* __restrict__ W, int M, int K) {
    __shared__ float Ws[768 * 8];
    int tid = threadIdx.x;
    for (int i = tid; i < K * 2; i += 256)
        ((float4*)Ws)[i] = ((const float4*)W)[i];
    __syncthreads();

    int wid = tid >> 5, lane = tid & 31;
    int base = (blockIdx.x * 8 + wid) * 4;
    if (base >= M) return;
    int nr = (M - base < 4) ? (M - base) : 4;

    float acc[4][8];
#pragma unroll
    for (int r = 0; r < 4; r++)
#pragma unroll
        for (int f = 0; f < 8; f++) acc[r][f] = 0.0f;

    const __half* a0 = g_h16 + (size_t)base * K;
    for (int k = lane; k < K; k += 32) {
        float4 w0 = *(const float4*)(Ws + k * 8);
        float4 w1 = *(const float4*)(Ws + k * 8 + 4);
        float av[4];
#pragma unroll
        for (int r = 0; r < 4; r++)
            av[r] = (r < nr) ? __half2float(a0[(size_t)r * K + k]) : 0.0f;
#pragma unroll
        for (int r = 0; r < 4; r++) {
            acc[r][0] += av[r] * w0.x; acc[r][1] += av[r] * w0.y;
            acc[r][2] += av[r] * w0.z; acc[r][3] += av[r] * w0.w;
            acc[r][4] += av[r] * w1.x; acc[r][5] += av[r] * w1.y;
            acc[r][6] += av[r] * w1.z; acc[r][7] += av[r] * w1.w;
        }
    }
#pragma unroll
    for (int r = 0; r < 4; r++)
#pragma unroll
        for (int f = 0; f < 8; f++)
#pragma unroll
            for (int o = 16; o > 0; o >>= 1)
                acc[r][f] += __shfl_down_sync(0xffffffffu, acc[r][f], o);
    if (lane == 0) {
#pragma unroll
        for (int r = 0; r < 4; r++)
            if (r < nr)
#pragma unroll
                for (int f = 0; f < 8; f++)
                    g_o8[(size_t)(base + r) * 8 + f] = acc[r][f];
    }
}

// ---------------- aggregation: fp16 gathers -> g_a16 FRAGMENT layout --------
// Pre-normalized weights; epilogue scatters fp16 m16n8k16 A fragments.
template <int F, int ASRC>
__global__ void __launch_bounds__(256)
k_agg(int n) {
    int gw = (blockIdx.x * blockDim.x + threadIdx.x) >> 5;
    int lane = threadIdx.x & 31;
    if (gw >= n) return;
    const __half* X = (ASRC == 0) ? g_x16 : g_h16;
    constexpr int NV = F / 128;
    constexpr int UN = (F == 256) ? 8 : 4;
    constexpr int K16 = F / 16;
    float dv = rsqrtf(g_deg[gw] + 1.0f);
    float4 acc[NV];
    const uint2* xr = (const uint2*)(X + (size_t)gw * F);
#pragma unroll
    for (int i = 0; i < NV; i++) {
        uint2 u = xr[lane + 32 * i];
        float2 lo = __half22float2(*reinterpret_cast<const __half2*>(&u.x));
        float2 hi = __half22float2(*reinterpret_cast<const __half2*>(&u.y));
        acc[i] = make_float4(lo.x * dv, lo.y * dv, hi.x * dv, hi.y * dv);
    }
    int cnt = g_cnt[gw];
    cnt = cnt > BCAP ? BCAP : cnt;
    const unsigned long long* eb = g_ebuf + (size_t)gw * BCAP;
    int j = 0;
    for (; j + UN <= cnt; j += UN) {
        const uint2* rp[UN];
        float wv[UN];
#pragma unroll
        for (int u = 0; u < UN; u++) {
            unsigned long long p = eb[j + u];
            int src = (int)(unsigned)p;
            wv[u] = __uint_as_float((unsigned)(p >> 32));
            rp[u] = (const uint2*)(X + (size_t)src * F);
        }
#pragma unroll
        for (int i = 0; i < NV; i++) {
            uint2 us[UN];
#pragma unroll
            for (int u = 0; u < UN; u++) us[u] = rp[u][lane + 32 * i];
#pragma unroll
            for (int u = 0; u < UN; u++) {
                float2 lo = __half22float2(*reinterpret_cast<const __half2*>(&us[u].x));
                float2 hi = __half22float2(*reinterpret_cast<const __half2*>(&us[u].y));
                acc[i].x += wv[u] * lo.x;
                acc[i].y += wv[u] * lo.y;
                acc[i].z += wv[u] * hi.x;
                acc[i].w += wv[u] * hi.y;
            }
        }
    }
    for (; j < cnt; j++) {
        unsigned long long p = eb[j];
        int src = (int)(unsigned)p;
        float w0 = __uint_as_float((unsigned)(p >> 32));
        const uint2* r0 = (const uint2*)(X + (size_t)src * F);
#pragma unroll
        for (int i = 0; i < NV; i++) {
            uint2 u = r0[lane + 32 * i];
            float2 lo = __half22float2(*reinterpret_cast<const __half2*>(&u.x));
            float2 hi = __half22float2(*reinterpret_cast<const __half2*>(&u.y));
            acc[i].x += w0 * lo.x;
            acc[i].y += w0 * lo.y;
            acc[i].z += w0 * hi.x;
            acc[i].w += w0 * hi.y;
        }
    }
    // scatter fp16 A fragments (m16n8k16):
    // lane covers cols c=4*lane+128*q -> k16=(lane>>2)+8q, pairs t0=2*(lane&1),
    // t0+1; hi8=(lane>>1)&1; slot s0 = (r16>=8) + 2*hi8; l' = 4*(r16&7)+t.
    int grp = gw >> 5, rr = gw & 31;
    int i16 = rr >> 4, r16 = rr & 15;
    int g = r16 & 7, sflag = r16 >> 3;
    int hi8 = (lane >> 1) & 1, t0 = 2 * (lane & 1);
    int s0 = sflag + 2 * hi8;
    int lp = 4 * g + t0;
#pragma unroll
    for (int q = 0; q < NV; q++) {
        int k16 = (lane >> 2) + 8 * q;
        long base = ((long)(grp * K16 + k16) * 2 + i16) * 128;
        __half2* dst = g_a16 + base + lp * 4 + s0;
        dst[0] = __floats2half2_rn(acc[q].x * dv, acc[q].y * dv);
        dst[4] = __floats2half2_rn(acc[q].z * dv, acc[q].w * dv);
    }
}

// ---------------- aggregation F=8 (+bias), writes d_out ---------------------
__global__ void k_agg8(const float* __restrict__ bias, float* __restrict__ out,
                       int n) {
    int v = blockIdx.x * blockDim.x + threadIdx.x;
    if (v >= n) return;
    float dv = rsqrtf(g_deg[v] + 1.0f);
    float acc[8];
    const float* xr = g_o8 + (size_t)v * 8;
#pragma unroll
    for (int f = 0; f < 8; f++) acc[f] = xr[f] * dv;
    int cnt = g_cnt[v];
    cnt = cnt > BCAP ? BCAP : cnt;
    const unsigned long long* eb = g_ebuf + (size_t)v * BCAP;
    for (int j = 0; j < cnt; j++) {
        unsigned long long p = eb[j];
        int src = (int)(unsigned)p;
        float w = __uint_as_float((unsigned)(p >> 32));
        const float* r = g_o8 + (size_t)src * 8;
#pragma unroll
        for (int f = 0; f < 8; f++) acc[f] += w * r[f];
    }
#pragma unroll
    for (int f = 0; f < 8; f++) out[(size_t)v * 8 + f] = acc[f] * dv + bias[f];
}

// ---------------- launch ----------------------------------------------------
extern "C" void kernel_launch(void* const* d_in, const int* in_sizes, int n_in,
                              void* d_out, int out_size) {
    const float* x  = (const float*)d_in[0];
    const void*  ei = d_in[1];
    const float* ew = (const float*)d_in[2];
    const float* W1 = (const float*)d_in[3];
    const float* b1 = (const float*)d_in[4];
    const float* W2 = (const float*)d_in[5];
    const float* b2 = (const float*)d_in[6];
    const float* W3 = (const float*)d_in[7];
    const float* b3 = (const float*)d_in[8];
    float* out = (float*)d_out;

    int N = in_sizes[0] / 256;
    int E = in_sizes[2];

    // ---- setup + weight prep + x conversion ----
    k_init_detect<<<(N + 255) / 256, 256>>>((const int*)ei, in_sizes[1], N);
    k_prep<<<(256 * 512 + 512 * 768 + 255) / 256, 256>>>(W1, W2);
    k_cvt<<<(N * 128 + 255) / 256, 256>>>(x, N * 128);
    k_pass1<<<(E + 255) / 256, 256>>>(ei, ew, E, N);
    k_norm<<<(N * 32 + 255) / 256, 256>>>(N);

    // ---- layer 1: agg(x16)@256 -> g_a16(frag); relu(g_a16@W1+b1) -> g_h16 ----
    k_agg<256, 0><<<(N * 32 + 255) / 256, 256>>>(N);
    k_gemm_fp16<0><<<dim3(512 / 64, (N + 127) / 128), 256>>>(b1, N, 256, 512);

    // ---- layer 2: agg(g_h16)@512 -> g_a16(frag); relu(g_a16@W2+b2) -> g_h16 ----
    k_agg<512, 1><<<(N * 32 + 255) / 256, 256>>>(N);
    k_gemm_fp16<1><<<dim3(768 / 64, (N + 127) / 128), 256>>>(b2, N, 512, 768);

    // ---- layer 3: g_h16@W3 -> g_o8; agg + bias -> out ----
    k_gemm8<<<(N + 31) / 32, 256>>>(W3, N, 768);
    k_agg8<<<(N + 255) / 256, 256>>>(b3, out, N);
}

// round 17
// speedup vs baseline: 1.6937x; 1.1185x over previous
#include <cuda_runtime.h>
#include <cuda_fp16.h>
#include <cstdint>

#define NMAX 10000
#define EMAX 320000
#define BCAP 128
#define AGRPS 316   // ceil(10112/32): A fragment groups incl. padding

// ---------------- scratch (static device globals; no allocation) ------------
__device__ int       g_is64;
__device__ float     g_deg[NMAX];
__device__ int       g_cnt[NMAX];
__device__ unsigned long long g_ebuf[(size_t)NMAX * BCAP];
__device__ __half2 g_a16[(size_t)AGRPS * 32 * 2 * 128]; // A fp16 frag layout
__device__ __half  g_x16[(size_t)NMAX * 256];           // fp16 copy of input x
__device__ __half  g_h16[(size_t)NMAX * 768];           // fp16 layer activation
__device__ __half2 g_wb1[256 * 512 / 2];                // W1 permuted fp16
__device__ __half2 g_wb2[512 * 768 / 2];                // W2 permuted fp16
__device__ float   g_o8[(size_t)NMAX * 8];

// ---------------- fused setup: init + detect + cvt(x) + prep(W1,W2) ---------
// All independent elementwise work in one launch.
__global__ void k_setup(const int* __restrict__ ei32, int nwords, int n,
                        const float* __restrict__ x, int ncvt2,
                        const float* __restrict__ W1,
                        const float* __restrict__ W2) {
    int g = blockIdx.x * 256 + threadIdx.x;
    // init deg/cnt
    if (g < n) { g_deg[g] = 0.0f; g_cnt[g] = 0; }
    // dtype detect (block 0 only)
    if (blockIdx.x == 0) {
        __shared__ int any_nonzero;
        if (threadIdx.x == 0) any_nonzero = 0;
        __syncthreads();
        int lim = nwords < 2048 ? nwords : 2048;
        for (int w = threadIdx.x * 2 + 1; w < lim; w += 512)
            if (ei32[w] != 0) atomicOr(&any_nonzero, 1);
        __syncthreads();
        if (threadIdx.x == 0) g_is64 = any_nonzero ? 0 : 1;
    }
    // x -> fp16
    if (g < ncvt2) {
        float2 v = ((const float2*)x)[g];
        ((__half2*)g_x16)[g] = __floats2half2_rn(v.x, v.y);
    }
    // weight permute+convert: W1 then W2
    if (g < 256 * 512) {
        int k = g >> 9, nn = g & 511;              // K=256 (K16=16), N=512
        __half v = __float2half_rn(W1[g]);
        int kr = k & 15;
        int grp = nn >> 5, j = (nn >> 3) & 3;
        int ln = 4 * (nn & 7) + ((kr >> 1) & 3);
        int slot = kr >> 3;
        long h2i = ((long)(grp * 16 + (k >> 4)) * 4 + j) * 64 + ln * 2 + slot;
        ((__half*)g_wb1)[h2i * 2 + (k & 1)] = v;
    }
    if (g >= 256 * 512 && g < 256 * 512 + 512 * 768) {
        int i2 = g - 256 * 512;
        int k = i2 / 768, nn = i2 - k * 768;       // K=512 (K16=32), N=768
        __half v = __float2half_rn(W2[i2]);
        int kr = k & 15;
        int grp = nn >> 5, j = (nn >> 3) & 3;
        int ln = 4 * (nn & 7) + ((kr >> 1) & 3);
        int slot = kr >> 3;
        long h2i = ((long)(grp * 32 + (k >> 4)) * 4 + j) * 64 + ln * 2 + slot;
        ((__half*)g_wb2)[h2i * 2 + (k & 1)] = v;
    }
}

__device__ __forceinline__ int load_idx(const void* ei, long long pos, int n) {
    int v = g_is64 ? (int)((const long long*)ei)[pos]
                   : ((const int*)ei)[pos];
    v = v < 0 ? 0 : (v >= n ? n - 1 : v);
    return v;
}

// ---------------- single edge pass: degree + bucket scatter ------------------
__global__ void k_pass1(const void* __restrict__ ei,
                        const float* __restrict__ ew, int E, int n) {
    int e = blockIdx.x * blockDim.x + threadIdx.x;
    if (e >= E) return;
    int r = load_idx(ei, e, n);
    int c = load_idx(ei, (long long)E + e, n);
    float w = ew[e];
    atomicAdd(&g_deg[c], w);
    int p = atomicAdd(&g_cnt[c], 1);
    if (p < BCAP) {
        unsigned long long packed =
            ((unsigned long long)__float_as_uint(w) << 32) | (unsigned)r;
        g_ebuf[(size_t)c * BCAP + p] = packed;
    }
}

// ---------------- normalize bucket weights: w -> w * rsqrt(deg[src]+1) ------
__global__ void k_norm(int n) {
    int gw = (blockIdx.x * blockDim.x + threadIdx.x) >> 5;
    int lane = threadIdx.x & 31;
    if (gw >= n) return;
    int cnt = g_cnt[gw];
    cnt = cnt > BCAP ? BCAP : cnt;
    unsigned long long* eb = g_ebuf + (size_t)gw * BCAP;
    for (int j = lane; j < cnt; j += 32) {
        unsigned long long p = eb[j];
        int src = (int)(unsigned)p;
        float w = __uint_as_float((unsigned)(p >> 32));
        w *= rsqrtf(g_deg[src] + 1.0f);
        eb[j] = ((unsigned long long)__float_as_uint(w) << 32) | (unsigned)src;
    }
}

// ---------------- helpers ----------------------------------------------------
__device__ __forceinline__ void cp_async8(uint32_t smem_addr, const void* gptr) {
    asm volatile("cp.async.ca.shared.global [%0], [%1], 8;"
                 :: "r"(smem_addr), "l"(gptr));
}
__device__ __forceinline__ void cp_commit() {
    asm volatile("cp.async.commit_group;");
}
__device__ __forceinline__ void cp_wait1() {
    asm volatile("cp.async.wait_group 1;");
}

// ---------------- FP16 TC GEMM (m16n8k16), fragment-layout operands ---------
template <int WSEL>
__global__ void __launch_bounds__(256)
k_gemm_fp16(const float* __restrict__ bias, int M, int K, int N) {
    __shared__ __half2 Bs[3][512];   // 3 stages x 2KB
    const __half2* Bp = WSEL ? (const __half2*)g_wb2 : (const __half2*)g_wb1;
    int tid = threadIdx.x;
    int lane = tid & 31, wid = tid >> 5;
    int wm = wid >> 1, wn = wid & 1;
    int bm = blockIdx.y * 128;
    int K16 = K >> 4;
    int agrp = blockIdx.y * 4 + wm;

    const uint4* Ap = (const uint4*)g_a16;
    long a_base = (long)agrp * K16 * 64 + lane;   // uint4 index

    int t_grp = tid >> 7;
    int t_off = (tid & 127) * 2;
    const __half2* b_src = Bp + ((size_t)(blockIdx.x * 2 + t_grp) * K16) * 256 + t_off;
    uint32_t bs0 = (uint32_t)__cvta_generic_to_shared(&Bs[0][0]);
    uint32_t boff = (t_grp * 256 + t_off) * 4;

    float acc[2][4][4];
#pragma unroll
    for (int i = 0; i < 2; i++)
#pragma unroll
        for (int j = 0; j < 4; j++)
#pragma unroll
            for (int r = 0; r < 4; r++) acc[i][j][r] = 0.0f;

    cp_async8(bs0 + boff, b_src);
    cp_commit();
    if (K16 > 1) cp_async8(bs0 + 2048 + boff, b_src + 256);
    cp_commit();

    uint4 af0 = Ap[a_base], af1 = Ap[a_base + 32];

    int st = 0, ld = 2;
    for (int it = 0; it < K16; it++) {
        cp_wait1();
        __syncthreads();
        if (it + 2 < K16)
            cp_async8(bs0 + ld * 2048 + boff, b_src + (size_t)(it + 2) * 256);
        cp_commit();

        uint4 aa[2] = {af0, af1};
        if (it + 1 < K16) {
            long nb = a_base + (long)(it + 1) * 64;
            af0 = Ap[nb];
            af1 = Ap[nb + 32];
        }

#pragma unroll
        for (int j = 0; j < 4; j++) {
            uint2 bb = *(const uint2*)&Bs[st][wn * 256 + j * 64 + lane * 2];
#pragma unroll
            for (int i = 0; i < 2; i++) {
                asm volatile(
                    "mma.sync.aligned.m16n8k16.row.col.f32.f16.f16.f32 "
                    "{%0,%1,%2,%3}, {%4,%5,%6,%7}, {%8,%9}, {%0,%1,%2,%3};\n"
                    : "+f"(acc[i][j][0]), "+f"(acc[i][j][1]),
                      "+f"(acc[i][j][2]), "+f"(acc[i][j][3])
                    : "r"(aa[i].x), "r"(aa[i].y), "r"(aa[i].z), "r"(aa[i].w),
                      "r"(bb.x), "r"(bb.y));
            }
        }
        st = (st == 2) ? 0 : st + 1;
        ld = (ld == 2) ? 0 : ld + 1;
    }

    // epilogue: bias + relu -> g_h16
    int bn = blockIdx.x * 64;
#pragma unroll
    for (int i = 0; i < 2; i++) {
#pragma unroll
        for (int j = 0; j < 4; j++) {
            int row = bm + wm * 32 + i * 16 + (lane >> 2);
            int col = bn + wn * 32 + j * 8 + (lane & 3) * 2;
            float b0 = __ldg(bias + col), b1 = __ldg(bias + col + 1);
            if (row < M) {
                *(__half2*)(g_h16 + (size_t)row * N + col) =
                    __floats2half2_rn(fmaxf(acc[i][j][0] + b0, 0.f),
                                      fmaxf(acc[i][j][1] + b1, 0.f));
            }
            if (row + 8 < M) {
                *(__half2*)(g_h16 + (size_t)(row + 8) * N + col) =
                    __floats2half2_rn(fmaxf(acc[i][j][2] + b0, 0.f),
                                      fmaxf(acc[i][j][3] + b1, 0.f));
            }
        }
    }
}

// ---------------- skinny GEMM N=8: W3 in SMEM, warp handles 4 rows ----------
__global__ void __launch_bounds__(256)
k_gemm8(const float* __restrict__ W, int M, int K) {
    __shared__ float Ws[768 * 8];
    int tid = threadIdx.x;
    for (int i = tid; i < K * 2; i += 256)
        ((float4*)Ws)[i] = ((const float4*)W)[i];
    __syncthreads();

    int wid = tid >> 5, lane = tid & 31;
    int base = (blockIdx.x * 8 + wid) * 4;
    if (base >= M) return;
    int nr = (M - base < 4) ? (M - base) : 4;

    float acc[4][8];
#pragma unroll
    for (int r = 0; r < 4; r++)
#pragma unroll
        for (int f = 0; f < 8; f++) acc[r][f] = 0.0f;

    const __half* a0 = g_h16 + (size_t)base * K;
    for (int k = lane; k < K; k += 32) {
        float4 w0 = *(const float4*)(Ws + k * 8);
        float4 w1 = *(const float4*)(Ws + k * 8 + 4);
        float av[4];
#pragma unroll
        for (int r = 0; r < 4; r++)
            av[r] = (r < nr) ? __half2float(a0[(size_t)r * K + k]) : 0.0f;
#pragma unroll
        for (int r = 0; r < 4; r++) {
            acc[r][0] += av[r] * w0.x; acc[r][1] += av[r] * w0.y;
            acc[r][2] += av[r] * w0.z; acc[r][3] += av[r] * w0.w;
            acc[r][4] += av[r] * w1.x; acc[r][5] += av[r] * w1.y;
            acc[r][6] += av[r] * w1.z; acc[r][7] += av[r] * w1.w;
        }
    }
#pragma unroll
    for (int r = 0; r < 4; r++)
#pragma unroll
        for (int f = 0; f < 8; f++)
#pragma unroll
            for (int o = 16; o > 0; o >>= 1)
                acc[r][f] += __shfl_down_sync(0xffffffffu, acc[r][f], o);
    if (lane == 0) {
#pragma unroll
        for (int r = 0; r < 4; r++)
            if (r < nr)
#pragma unroll
                for (int f = 0; f < 8; f++)
                    g_o8[(size_t)(base + r) * 8 + f] = acc[r][f];
    }
}

// ---------------- aggregation: fp16 gathers -> g_a16 FRAGMENT layout --------
// UN=8 for both widths; 32-bit element offsets to limit register pressure.
template <int F, int ASRC>
__global__ void __launch_bounds__(256)
k_agg(int n) {
    int gw = (blockIdx.x * blockDim.x + threadIdx.x) >> 5;
    int lane = threadIdx.x & 31;
    if (gw >= n) return;
    const __half* X = (ASRC == 0) ? g_x16 : g_h16;
    constexpr int NV = F / 128;
    constexpr int UN = 8;
    constexpr int K16 = F / 16;
    float dv = rsqrtf(g_deg[gw] + 1.0f);
    float4 acc[NV];
    const uint2* xr = (const uint2*)(X + (size_t)gw * F);
#pragma unroll
    for (int i = 0; i < NV; i++) {
        uint2 u = xr[lane + 32 * i];
        float2 lo = __half22float2(*reinterpret_cast<const __half2*>(&u.x));
        float2 hi = __half22float2(*reinterpret_cast<const __half2*>(&u.y));
        acc[i] = make_float4(lo.x * dv, lo.y * dv, hi.x * dv, hi.y * dv);
    }
    int cnt = g_cnt[gw];
    cnt = cnt > BCAP ? BCAP : cnt;
    const unsigned long long* eb = g_ebuf + (size_t)gw * BCAP;
    const uint2* Xu = (const uint2*)X;
    int j = 0;
    for (; j + UN <= cnt; j += UN) {
        int offs[UN];
        float wv[UN];
#pragma unroll
        for (int u = 0; u < UN; u++) {
            unsigned long long p = eb[j + u];
            int src = (int)(unsigned)p;
            wv[u] = __uint_as_float((unsigned)(p >> 32));
            offs[u] = src * (F / 4) + lane;   // uint2 index of lane's quad
        }
#pragma unroll
        for (int i = 0; i < NV; i++) {
            uint2 us[UN];
#pragma unroll
            for (int u = 0; u < UN; u++) us[u] = Xu[offs[u] + 32 * i];
#pragma unroll
            for (int u = 0; u < UN; u++) {
                float2 lo = __half22float2(*reinterpret_cast<const __half2*>(&us[u].x));
                float2 hi = __half22float2(*reinterpret_cast<const __half2*>(&us[u].y));
                acc[i].x += wv[u] * lo.x;
                acc[i].y += wv[u] * lo.y;
                acc[i].z += wv[u] * hi.x;
                acc[i].w += wv[u] * hi.y;
            }
        }
    }
    for (; j < cnt; j++) {
        unsigned long long p = eb[j];
        int src = (int)(unsigned)p;
        float w0 = __uint_as_float((unsigned)(p >> 32));
        const uint2* r0 = Xu + src * (F / 4);
#pragma unroll
        for (int i = 0; i < NV; i++) {
            uint2 u = r0[lane + 32 * i];
            float2 lo = __half22float2(*reinterpret_cast<const __half2*>(&u.x));
            float2 hi = __half22float2(*reinterpret_cast<const __half2*>(&u.y));
            acc[i].x += w0 * lo.x;
            acc[i].y += w0 * lo.y;
            acc[i].z += w0 * hi.x;
            acc[i].w += w0 * hi.y;
        }
    }
    // scatter fp16 A fragments (m16n8k16)
    int grp = gw >> 5, rr = gw & 31;
    int i16 = rr >> 4, r16 = rr & 15;
    int g = r16 & 7, sflag = r16 >> 3;
    int hi8 = (lane >> 1) & 1, t0 = 2 * (lane & 1);
    int s0 = sflag + 2 * hi8;
    int lp = 4 * g + t0;
#pragma unroll
    for (int q = 0; q < NV; q++) {
        int k16 = (lane >> 2) + 8 * q;
        long base = ((long)(grp * K16 + k16) * 2 + i16) * 128;
        __half2* dst = g_a16 + base + lp * 4 + s0;
        dst[0] = __floats2half2_rn(acc[q].x * dv, acc[q].y * dv);
        dst[4] = __floats2half2_rn(acc[q].z * dv, acc[q].w * dv);
    }
}

// ---------------- aggregation F=8 (+bias): thread per (node, f) -------------
__global__ void k_agg8(const float* __restrict__ bias, float* __restrict__ out,
                       int n) {
    int t = blockIdx.x * blockDim.x + threadIdx.x;
    int v = t >> 3, f = t & 7;
    if (v >= n) return;
    float dv = rsqrtf(g_deg[v] + 1.0f);
    float acc = g_o8[(size_t)v * 8 + f] * dv;
    int cnt = g_cnt[v];
    cnt = cnt > BCAP ? BCAP : cnt;
    const unsigned long long* eb = g_ebuf + (size_t)v * BCAP;
    int j = 0;
    for (; j + 4 <= cnt; j += 4) {
        float s = 0.0f;
#pragma unroll
        for (int u = 0; u < 4; u++) {
            unsigned long long p = eb[j + u];
            int src = (int)(unsigned)p;
            float w = __uint_as_float((unsigned)(p >> 32));
            s += w * g_o8[(size_t)src * 8 + f];
        }
        acc += s;
    }
    for (; j < cnt; j++) {
        unsigned long long p = eb[j];
        int src = (int)(unsigned)p;
        float w = __uint_as_float((unsigned)(p >> 32));
        acc += w * g_o8[(size_t)src * 8 + f];
    }
    out[(size_t)v * 8 + f] = acc * dv + bias[f];
}

// ---------------- launch ----------------------------------------------------
extern "C" void kernel_launch(void* const* d_in, const int* in_sizes, int n_in,
                              void* d_out, int out_size) {
    const float* x  = (const float*)d_in[0];
    const void*  ei = d_in[1];
    const float* ew = (const float*)d_in[2];
    const float* W1 = (const float*)d_in[3];
    const float* b1 = (const float*)d_in[4];
    const float* W2 = (const float*)d_in[5];
    const float* b2 = (const float*)d_in[6];
    const float* W3 = (const float*)d_in[7];
    const float* b3 = (const float*)d_in[8];
    float* out = (float*)d_out;

    int N = in_sizes[0] / 256;
    int E = in_sizes[2];
    int ncvt2 = N * 128;
    int setup_blocks = (ncvt2 + 255) / 256;   // covers cvt (largest range)
    {
        int wblocks = (256 * 512 + 512 * 768 + 255) / 256;
        if (wblocks > setup_blocks) setup_blocks = wblocks;
        int nblocks = (N + 255) / 256;
        if (nblocks > setup_blocks) setup_blocks = nblocks;
    }

    // ---- fused setup (init+detect+cvt+prep), then edge passes ----
    k_setup<<<setup_blocks, 256>>>((const int*)ei, in_sizes[1], N,
                                   x, ncvt2, W1, W2);
    k_pass1<<<(E + 255) / 256, 256>>>(ei, ew, E, N);
    k_norm<<<(N * 32 + 255) / 256, 256>>>(N);

    // ---- layer 1 ----
    k_agg<256, 0><<<(N * 32 + 255) / 256, 256>>>(N);
    k_gemm_fp16<0><<<dim3(512 / 64, (N + 127) / 128), 256>>>(b1, N, 256, 512);

    // ---- layer 2 ----
    k_agg<512, 1><<<(N * 32 + 255) / 256, 256>>>(N);
    k_gemm_fp16<1><<<dim3(768 / 64, (N + 127) / 128), 256>>>(b2, N, 512, 768);

    // ---- layer 3 ----
    k_gemm8<<<(N + 31) / 32, 256>>>(W3, N, 768);
    k_agg8<<<(N * 8 + 255) / 256, 256>>>(b3, out, N);
}